// round 1
// baseline (speedup 1.0000x reference)
#include <cuda_runtime.h>
#include <cuda_bf16.h>

// Problem constants
#define EDIM   512
#define MROWS  32768
#define HDIM   1024       // FFN hidden = 2*E
#define LN_EPS 1e-5f

// Dynamic smem: Xs[32][64] + Ws[32][512] floats
#define SMEM_FLOATS (32*64 + 32*512)
#define SMEM_BYTES  (SMEM_FLOATS * 4)

// ---------------------------------------------------------------------------
// Scratch (no cudaMalloc allowed): fused weights, bias, X1, H for both streams
// ---------------------------------------------------------------------------
__device__ float g_Wvo[2 * EDIM * EDIM];
__device__ float g_bvo[2 * EDIM];
__device__ float g_X1 [2l * MROWS * EDIM];   // post first LN
__device__ float g_H  [2l * MROWS * HDIM];   // relu(ffn up)

// ---------------------------------------------------------------------------
// Packed fp32x2 FMA (sm_100+): 2x scalar FFMA throughput
// ---------------------------------------------------------------------------
__device__ __forceinline__ void fma2(float2& d, const float2& a, const float2& b) {
    unsigned long long* dp = reinterpret_cast<unsigned long long*>(&d);
    asm("fma.rn.f32x2 %0, %1, %2, %0;"
        : "+l"(*dp)
        : "l"(*reinterpret_cast<const unsigned long long*>(&a)),
          "l"(*reinterpret_cast<const unsigned long long*>(&b)));
}

// ---------------------------------------------------------------------------
// Fused GEMM: out[m, n] = epilogue( sum_k X[m,k] * W[n_off+n, k] + bias[n_off+n] )
//   EPI == 0 : += resid[m, n]; row LayerNorm over full 512 cols; *g + b
//   EPI == 1 : relu
// BM=64, BN=512 (full row -> LN feasible in-block), BK=32, 512 threads.
// Thread (wr = t/32, wc = t%32): rows wr*4..+3, cols {wc*4 + seg*128 + e}.
// ---------------------------------------------------------------------------
template<int EPI>
__global__ __launch_bounds__(512, 1)
void gemm_fused(const float* __restrict__ X,
                const float* __restrict__ W,
                int K,
                const float* __restrict__ bias,
                const float* __restrict__ resid,
                const float* __restrict__ lng,
                const float* __restrict__ lnb,
                float* __restrict__ out,
                int out_stride, int out_coloff)
{
    extern __shared__ float smem[];
    float* Xs = smem;            // [kk][m]  : 32 x 64
    float* Ws = smem + 32 * 64;  // [kk][n]  : 32 x 512

    const int t     = threadIdx.x;
    const int wr    = t >> 5;
    const int wc    = t & 31;
    const int row0  = blockIdx.x * 64;
    const int n_off = blockIdx.y * 512;

    float2 acc[4][8];
    #pragma unroll
    for (int i = 0; i < 4; i++)
        #pragma unroll
        for (int p = 0; p < 8; p++) acc[i][p] = make_float2(0.f, 0.f);

    const int xr = t & 63;    // X-loader row
    const int xq = t >> 6;    // X-loader k-quad (0..7)

    for (int kt = 0; kt < K; kt += 32) {
        // Load X tile (64 rows x 32 k), transposed into Xs[kk][m]
        {
            float4 xv = *reinterpret_cast<const float4*>(
                X + (size_t)(row0 + xr) * K + kt + xq * 4);
            Xs[(xq * 4 + 0) * 64 + xr] = xv.x;
            Xs[(xq * 4 + 1) * 64 + xr] = xv.y;
            Xs[(xq * 4 + 2) * 64 + xr] = xv.z;
            Xs[(xq * 4 + 3) * 64 + xr] = xv.w;
        }
        // Load W tile (512 n x 32 k), transposed into Ws[kk][n]; one n per thread
        {
            const float* wrow = W + (size_t)(n_off + t) * K + kt;
            #pragma unroll
            for (int q = 0; q < 8; q++) {
                float4 wv = *reinterpret_cast<const float4*>(wrow + q * 4);
                Ws[(q * 4 + 0) * 512 + t] = wv.x;
                Ws[(q * 4 + 1) * 512 + t] = wv.y;
                Ws[(q * 4 + 2) * 512 + t] = wv.z;
                Ws[(q * 4 + 3) * 512 + t] = wv.w;
            }
        }
        __syncthreads();

        #pragma unroll
        for (int kk = 0; kk < 32; kk++) {
            float4 a4 = *reinterpret_cast<const float4*>(Xs + kk * 64 + wr * 4);
            float2 ai[4];
            ai[0] = make_float2(a4.x, a4.x);
            ai[1] = make_float2(a4.y, a4.y);
            ai[2] = make_float2(a4.z, a4.z);
            ai[3] = make_float2(a4.w, a4.w);
            #pragma unroll
            for (int seg = 0; seg < 4; seg++) {
                float4 b4 = *reinterpret_cast<const float4*>(
                    Ws + kk * 512 + seg * 128 + wc * 4);
                float2 blo = make_float2(b4.x, b4.y);
                float2 bhi = make_float2(b4.z, b4.w);
                #pragma unroll
                for (int i = 0; i < 4; i++) {
                    fma2(acc[i][seg * 2 + 0], ai[i], blo);
                    fma2(acc[i][seg * 2 + 1], ai[i], bhi);
                }
            }
        }
        __syncthreads();
    }

    // ---------------- epilogue ----------------
    const int colb = wc * 4;
    const int m0   = row0 + wr * 4;

    float4 bias4[4];
    #pragma unroll
    for (int s = 0; s < 4; s++)
        bias4[s] = *reinterpret_cast<const float4*>(bias + n_off + s * 128 + colb);

    float4 g4[4], be4[4];
    if (EPI == 0) {
        #pragma unroll
        for (int s = 0; s < 4; s++) {
            g4[s]  = *reinterpret_cast<const float4*>(lng + s * 128 + colb);
            be4[s] = *reinterpret_cast<const float4*>(lnb + s * 128 + colb);
        }
    }

    #pragma unroll
    for (int i = 0; i < 4; i++) {
        const int m = m0 + i;
        float v[16];
        #pragma unroll
        for (int s = 0; s < 4; s++) {
            v[s * 4 + 0] = acc[i][s * 2 + 0].x;
            v[s * 4 + 1] = acc[i][s * 2 + 0].y;
            v[s * 4 + 2] = acc[i][s * 2 + 1].x;
            v[s * 4 + 3] = acc[i][s * 2 + 1].y;
        }
        // + bias
        v[0]  += bias4[0].x; v[1]  += bias4[0].y; v[2]  += bias4[0].z; v[3]  += bias4[0].w;
        v[4]  += bias4[1].x; v[5]  += bias4[1].y; v[6]  += bias4[1].z; v[7]  += bias4[1].w;
        v[8]  += bias4[2].x; v[9]  += bias4[2].y; v[10] += bias4[2].z; v[11] += bias4[2].w;
        v[12] += bias4[3].x; v[13] += bias4[3].y; v[14] += bias4[3].z; v[15] += bias4[3].w;

        float* op = out + (size_t)m * out_stride + out_coloff + n_off;

        if (EPI == 1) {
            #pragma unroll
            for (int s = 0; s < 4; s++) {
                float4 o;
                o.x = fmaxf(v[s * 4 + 0], 0.f);
                o.y = fmaxf(v[s * 4 + 1], 0.f);
                o.z = fmaxf(v[s * 4 + 2], 0.f);
                o.w = fmaxf(v[s * 4 + 3], 0.f);
                *reinterpret_cast<float4*>(op + s * 128 + colb) = o;
            }
        } else {
            // residual
            #pragma unroll
            for (int s = 0; s < 4; s++) {
                float4 r = *reinterpret_cast<const float4*>(
                    resid + (size_t)m * 512 + s * 128 + colb);
                v[s * 4 + 0] += r.x; v[s * 4 + 1] += r.y;
                v[s * 4 + 2] += r.z; v[s * 4 + 3] += r.w;
            }
            // mean
            float ssum = 0.f;
            #pragma unroll
            for (int j = 0; j < 16; j++) ssum += v[j];
            #pragma unroll
            for (int off = 16; off > 0; off >>= 1)
                ssum += __shfl_xor_sync(0xffffffffu, ssum, off);
            const float mean = ssum * (1.0f / 512.0f);
            // var
            float sq = 0.f;
            #pragma unroll
            for (int j = 0; j < 16; j++) { float d = v[j] - mean; sq += d * d; }
            #pragma unroll
            for (int off = 16; off > 0; off >>= 1)
                sq += __shfl_xor_sync(0xffffffffu, sq, off);
            const float rs = rsqrtf(sq * (1.0f / 512.0f) + LN_EPS);

            const float gg[16] = {g4[0].x, g4[0].y, g4[0].z, g4[0].w,
                                  g4[1].x, g4[1].y, g4[1].z, g4[1].w,
                                  g4[2].x, g4[2].y, g4[2].z, g4[2].w,
                                  g4[3].x, g4[3].y, g4[3].z, g4[3].w};
            const float bb[16] = {be4[0].x, be4[0].y, be4[0].z, be4[0].w,
                                  be4[1].x, be4[1].y, be4[1].z, be4[1].w,
                                  be4[2].x, be4[2].y, be4[2].z, be4[2].w,
                                  be4[3].x, be4[3].y, be4[3].z, be4[3].w};
            #pragma unroll
            for (int s = 0; s < 4; s++) {
                float4 o;
                o.x = (v[s * 4 + 0] - mean) * rs * gg[s * 4 + 0] + bb[s * 4 + 0];
                o.y = (v[s * 4 + 1] - mean) * rs * gg[s * 4 + 1] + bb[s * 4 + 1];
                o.z = (v[s * 4 + 2] - mean) * rs * gg[s * 4 + 2] + bb[s * 4 + 2];
                o.w = (v[s * 4 + 3] - mean) * rs * gg[s * 4 + 3] + bb[s * 4 + 3];
                *reinterpret_cast<float4*>(op + s * 128 + colb) = o;
            }
        }
    }
}

// ---------------------------------------------------------------------------
// Wvo[j,m] = sum_k Wo[j,k] * Wv[k,m]   (512x512x512, tiny one-shot GEMM)
// ---------------------------------------------------------------------------
__global__ void fuse_w_kernel(const float* __restrict__ Wo,
                              const float* __restrict__ Wv,
                              float* __restrict__ Wvo)
{
    __shared__ float As[32][33];
    __shared__ float Bs[32][33];
    const int tx = threadIdx.x, ty = threadIdx.y;       // 16x16
    const int j0 = blockIdx.y * 32, m0 = blockIdx.x * 32;
    float a00 = 0.f, a01 = 0.f, a10 = 0.f, a11 = 0.f;

    for (int k0 = 0; k0 < 512; k0 += 32) {
        for (int idx = ty * 16 + tx; idx < 1024; idx += 256) {
            int r = idx >> 5, c = idx & 31;
            As[r][c] = Wo[(j0 + r) * 512 + k0 + c];
            Bs[r][c] = Wv[(k0 + r) * 512 + m0 + c];
        }
        __syncthreads();
        #pragma unroll
        for (int kk = 0; kk < 32; kk++) {
            float x0 = As[ty][kk], x1 = As[ty + 16][kk];
            float y0 = Bs[kk][tx], y1 = Bs[kk][tx + 16];
            a00 += x0 * y0; a01 += x0 * y1;
            a10 += x1 * y0; a11 += x1 * y1;
        }
        __syncthreads();
    }
    Wvo[(j0 + ty)      * 512 + m0 + tx]      = a00;
    Wvo[(j0 + ty)      * 512 + m0 + tx + 16] = a01;
    Wvo[(j0 + ty + 16) * 512 + m0 + tx]      = a10;
    Wvo[(j0 + ty + 16) * 512 + m0 + tx + 16] = a11;
}

// bvo[j] = sum_k Wo[j,k]*bv[k] + bo[j]
__global__ void bvo_kernel(const float* __restrict__ Wo,
                           const float* __restrict__ bv,
                           const float* __restrict__ bo,
                           float* __restrict__ bvo)
{
    const int warp = (blockIdx.x * blockDim.x + threadIdx.x) >> 5;
    const int lane = threadIdx.x & 31;
    if (warp >= 512) return;
    float s = 0.f;
    for (int k = lane; k < 512; k += 32) s += Wo[warp * 512 + k] * bv[k];
    #pragma unroll
    for (int off = 16; off > 0; off >>= 1)
        s += __shfl_xor_sync(0xffffffffu, s, off);
    if (lane == 0) bvo[warp] = s + bo[warp];
}

// ---------------------------------------------------------------------------
// kernel_launch
// ---------------------------------------------------------------------------
extern "C" void kernel_launch(void* const* d_in, const int* in_sizes, int n_in,
                              void* d_out, int out_size)
{
    const float* dna   = (const float*)d_in[0];
    const float* mol   = (const float*)d_in[1];
    const float* in_w[2]  = {(const float*)d_in[2], (const float*)d_in[6]};
    const float* in_b[2]  = {(const float*)d_in[3], (const float*)d_in[7]};
    const float* out_w[2] = {(const float*)d_in[4], (const float*)d_in[8]};
    const float* out_b[2] = {(const float*)d_in[5], (const float*)d_in[9]};
    const float* lnA_g[2] = {(const float*)d_in[10], (const float*)d_in[12]};
    const float* lnA_b[2] = {(const float*)d_in[11], (const float*)d_in[13]};
    const float* lnC_g[2] = {(const float*)d_in[14], (const float*)d_in[16]};
    const float* lnC_b[2] = {(const float*)d_in[15], (const float*)d_in[17]};
    const float* w1[2] = {(const float*)d_in[18], (const float*)d_in[22]};
    const float* b1[2] = {(const float*)d_in[19], (const float*)d_in[23]};
    const float* w2[2] = {(const float*)d_in[20], (const float*)d_in[24]};
    const float* b2[2] = {(const float*)d_in[21], (const float*)d_in[25]};

    float* out = (float*)d_out;

    float *Wvo, *bvo, *X1, *Hbuf;
    cudaGetSymbolAddress((void**)&Wvo,  g_Wvo);
    cudaGetSymbolAddress((void**)&bvo,  g_bvo);
    cudaGetSymbolAddress((void**)&X1,   g_X1);
    cudaGetSymbolAddress((void**)&Hbuf, g_H);

    cudaFuncSetAttribute(gemm_fused<0>, cudaFuncAttributeMaxDynamicSharedMemorySize, SMEM_BYTES);
    cudaFuncSetAttribute(gemm_fused<1>, cudaFuncAttributeMaxDynamicSharedMemorySize, SMEM_BYTES);

    const float* kv[2] = {mol, dna};   // stream 0 (dna side) attends over mol
    const float* xr[2] = {dna, mol};

    // Fuse Wo @ Wv and biases for both streams
    for (int s = 0; s < 2; s++) {
        const float* Wv = in_w[s] + 2 * EDIM * EDIM;  // third block of in_w
        const float* bv = in_b[s] + 2 * EDIM;
        fuse_w_kernel<<<dim3(16, 16), dim3(16, 16)>>>(out_w[s], Wv, Wvo + (size_t)s * EDIM * EDIM);
        bvo_kernel<<<64, 256>>>(out_w[s], bv, out_b[s], bvo + s * EDIM);
    }

    for (int s = 0; s < 2; s++) {
        float* x1 = X1   + (size_t)s * MROWS * EDIM;
        float* hh = Hbuf + (size_t)s * MROWS * HDIM;

        // K_A: x1 = LN( x + kv @ Wvo^T + bvo )
        gemm_fused<0><<<dim3(MROWS / 64, 1), 512, SMEM_BYTES>>>(
            kv[s], Wvo + (size_t)s * EDIM * EDIM, EDIM,
            bvo + s * EDIM, xr[s], lnA_g[s], lnA_b[s],
            x1, EDIM, 0);

        // K_B: H = relu( x1 @ W1^T + b1 )   (N=1024 split in 2)
        gemm_fused<1><<<dim3(MROWS / 64, 2), 512, SMEM_BYTES>>>(
            x1, w1[s], EDIM,
            b1[s], nullptr, nullptr, nullptr,
            hh, HDIM, 0);

        // K_C: out_half = LN( x1 + H @ W2^T + b2 )
        gemm_fused<0><<<dim3(MROWS / 64, 1), 512, SMEM_BYTES>>>(
            hh, w2[s], HDIM,
            b2[s], x1, lnC_g[s], lnC_b[s],
            out, 2 * EDIM, s * EDIM);
    }
}

// round 4
// speedup vs baseline: 2.4958x; 2.4958x over previous
#include <cuda_runtime.h>
#include <cuda_bf16.h>
#include <cstdint>

#define EDIM   512
#define MROWS  32768
#define HDIM   1024
#define LN_EPS 1e-5f

// ---------------- mma.sync GEMM tiling ----------------
#define BM 128
#define BN 128
#define BK 32
#define NTHR 256

// smem: 4 arrays (Ah, Al, Bh, Bl), 128 rows x 32 bf16, row stride 80B (conflict-free ldmatrix)
#define ROWB   80
#define ARRB   (128 * ROWB)          // 10240
#define STAGEB (4 * ARRB)            // 40960
#define DYN_SMEM (2 * STAGEB)        // 81920

#define MN (MROWS * EDIM)            // 16777216
#define MH (MROWS * HDIM)            // 33554432
#define WOFF_VO 0
#define WOFF_W1 262144
#define WOFF_W2 786432
#define WSTRIDE 1310720

// ---------------- device scratch (no cudaMalloc allowed) ----------------
__device__ float          g_Wf [2 * EDIM * EDIM];
__device__ float          g_bvo[2 * EDIM];
__device__ __nv_bfloat16  g_wh [2 * WSTRIDE];
__device__ __nv_bfloat16  g_wl [2 * WSTRIDE];
__device__ __nv_bfloat16  g_xh [2 * MN];
__device__ __nv_bfloat16  g_xl [2 * MN];
__device__ __nv_bfloat16  g_x1h[2 * MN];
__device__ __nv_bfloat16  g_x1l[2 * MN];
__device__ __nv_bfloat16  g_hh [2l * MH];
__device__ __nv_bfloat16  g_hl [2l * MH];
__device__ float          g_Y  [MN];

// ---------------- PTX helpers ----------------
__device__ __forceinline__ uint32_t smem_u32(const void* p) {
    uint32_t a;
    asm("{ .reg .u64 t; cvta.to.shared.u64 t, %1; cvt.u32.u64 %0, t; }" : "=r"(a) : "l"(p));
    return a;
}
__device__ __forceinline__ void ldsm4(uint32_t* r, uint32_t addr) {
    asm volatile("ldmatrix.sync.aligned.x4.m8n8.shared.b16 {%0,%1,%2,%3}, [%4];"
                 : "=r"(r[0]), "=r"(r[1]), "=r"(r[2]), "=r"(r[3]) : "r"(addr));
}
__device__ __forceinline__ void mma_bf16(float* c, const uint32_t* a, const uint32_t* b) {
    asm volatile(
        "mma.sync.aligned.m16n8k16.row.col.f32.bf16.bf16.f32 "
        "{%0,%1,%2,%3}, {%4,%5,%6,%7}, {%8,%9}, {%0,%1,%2,%3};"
        : "+f"(c[0]), "+f"(c[1]), "+f"(c[2]), "+f"(c[3])
        : "r"(a[0]), "r"(a[1]), "r"(a[2]), "r"(a[3]), "r"(b[0]), "r"(b[1]));
}
__device__ __forceinline__ void cp16(uint32_t dst, const void* src) {
    asm volatile("cp.async.cg.shared.global [%0], [%1], 16;" :: "r"(dst), "l"(src) : "memory");
}

// ---------------------------------------------------------------------------
// GEMM: C[row0+128, ncol0+128] = A[M,K] @ B[N,K]^T (both K-major, bf16 hi/lo)
// acc = Ah*Bh + Ah*Bl + Al*Bh (fp32 mma accumulation)
// EPI 0: Yout = acc + bias (fp32).  EPI 1: Oh/Ol = split(relu(acc + bias)).
// ---------------------------------------------------------------------------
template<int EPI>
__global__ __launch_bounds__(NTHR)
void gemm_mma(const __nv_bfloat16* __restrict__ Ah_, const __nv_bfloat16* __restrict__ Al_, int lda,
              const __nv_bfloat16* __restrict__ Bh_, const __nv_bfloat16* __restrict__ Bl_, int ldb,
              int K, const float* __restrict__ bias,
              float* __restrict__ Yout, int ldy,
              __nv_bfloat16* __restrict__ Oh, __nv_bfloat16* __restrict__ Ol, int ldo)
{
    extern __shared__ char smraw[];
    const uint32_t sb = smem_u32(smraw);

    const int t  = threadIdx.x;
    const int l  = t & 31;
    const int w  = t >> 5;
    const int wr = w >> 2;            // 0..1  (M)
    const int wn = w & 3;             // 0..3  (N)
    const int ncol0 = blockIdx.x * BN;   // N fastest -> A tile L2 reuse
    const int row0  = blockIdx.y * BM;

    // --- per-thread cp.async plan: 8 x 16B per chunk ---
    const __nv_bfloat16* srcbase[8];
    uint32_t dstoff[8];
    {
        const __nv_bfloat16* srcs[4] = {Ah_, Al_, Bh_, Bl_};
        #pragma unroll
        for (int j = 0; j < 8; j++) {
            const int u   = t + j * NTHR;       // 0..2047
            const int arr = u >> 9;             // 0..3
            const int i   = u & 511;
            const int row = i >> 2;             // 0..127
            const int c   = i & 3;              // 16B chunk
            const int gr0 = (arr < 2) ? row0 : ncol0;
            const int ld  = (arr < 2) ? lda : ldb;
            srcbase[j] = srcs[arr] + (size_t)(gr0 + row) * ld + c * 8;
            dstoff[j]  = arr * ARRB + row * ROWB + c * 16;
        }
    }

    float acc[4][4][4];
    #pragma unroll
    for (int mt = 0; mt < 4; mt++)
        #pragma unroll
        for (int nt = 0; nt < 4; nt++)
            #pragma unroll
            for (int e = 0; e < 4; e++) acc[mt][nt][e] = 0.f;

    const int nch = K / BK;

    // prologue: fill stages 0,1
    #pragma unroll
    for (int s = 0; s < 2; s++) {
        const int kt = s * BK;
        #pragma unroll
        for (int j = 0; j < 8; j++) cp16(sb + s * STAGEB + dstoff[j], srcbase[j] + kt);
        asm volatile("cp.async.commit_group;" ::: "memory");
    }

    // ldmatrix address components (constant across chunks)
    const uint32_t a_row = (uint32_t)(wr * 64 + (l & 15)) * ROWB;
    const uint32_t a_chk = (uint32_t)(l >> 4) << 4;                 // 0 / 16
    const uint32_t b_row0 = (uint32_t)(wn * 32 + (l >> 4) * 8 + (l & 7)) * ROWB;
    const uint32_t b_chk = (uint32_t)((l >> 3) & 1) << 4;

    for (int ch = 0; ch < nch; ch++) {
        if (ch == nch - 1) asm volatile("cp.async.wait_group 0;" ::: "memory");
        else               asm volatile("cp.async.wait_group 1;" ::: "memory");
        __syncthreads();

        const uint32_t sA = sb + (ch & 1) * STAGEB;
        #pragma unroll
        for (int ks = 0; ks < 2; ks++) {
            const uint32_t koff = (uint32_t)(ks * 2) << 4;
            uint32_t a_h[4][4], a_l[4][4];
            #pragma unroll
            for (int mt = 0; mt < 4; mt++) {
                const uint32_t ad = sA + a_row + (uint32_t)(mt * 16) * ROWB + koff + a_chk;
                ldsm4(a_h[mt], ad);
                ldsm4(a_l[mt], ad + ARRB);
            }
            uint32_t b_h[2][4], b_l[2][4];
            #pragma unroll
            for (int p = 0; p < 2; p++) {
                const uint32_t bd = sA + 2 * ARRB + b_row0 + (uint32_t)(p * 16) * ROWB + koff + b_chk;
                ldsm4(b_h[p], bd);
                ldsm4(b_l[p], bd + ARRB);
            }
            #pragma unroll
            for (int mt = 0; mt < 4; mt++)
                #pragma unroll
                for (int nt = 0; nt < 4; nt++) {
                    float* c = acc[mt][nt];
                    const uint32_t* bh = &b_h[nt >> 1][(nt & 1) * 2];
                    const uint32_t* bl = &b_l[nt >> 1][(nt & 1) * 2];
                    mma_bf16(c, a_h[mt], bh);
                    mma_bf16(c, a_h[mt], bl);
                    mma_bf16(c, a_l[mt], bh);
                }
        }
        __syncthreads();
        if (ch + 2 < nch) {
            const int kt = (ch + 2) * BK;
            const uint32_t sD = sb + (ch & 1) * STAGEB;
            #pragma unroll
            for (int j = 0; j < 8; j++) cp16(sD + dstoff[j], srcbase[j] + kt);
            asm volatile("cp.async.commit_group;" ::: "memory");
        } else {
            asm volatile("cp.async.commit_group;" ::: "memory");  // keep group count in lockstep
        }
    }

    // ---------------- epilogue ----------------
    #pragma unroll
    for (int mt = 0; mt < 4; mt++) {
        #pragma unroll
        for (int nt = 0; nt < 4; nt++) {
            const int r_base = row0 + wr * 64 + mt * 16 + (l >> 2);
            const int gcol   = ncol0 + wn * 32 + nt * 8 + (l & 3) * 2;
            const float b0v = bias[gcol];
            const float b1v = bias[gcol + 1];
            #pragma unroll
            for (int h = 0; h < 2; h++) {
                float v0 = acc[mt][nt][h * 2 + 0] + b0v;
                float v1 = acc[mt][nt][h * 2 + 1] + b1v;
                const size_t ro = (size_t)(r_base + h * 8);
                if (EPI == 1) {
                    v0 = fmaxf(v0, 0.f);
                    v1 = fmaxf(v1, 0.f);
                    const __nv_bfloat16 h0 = __float2bfloat16(v0);
                    const __nv_bfloat16 h1 = __float2bfloat16(v1);
                    const __nv_bfloat16 l0 = __float2bfloat16(v0 - __bfloat162float(h0));
                    const __nv_bfloat16 l1 = __float2bfloat16(v1 - __bfloat162float(h1));
                    *reinterpret_cast<__nv_bfloat162*>(Oh + ro * ldo + gcol) = __halves2bfloat162(h0, h1);
                    *reinterpret_cast<__nv_bfloat162*>(Ol + ro * ldo + gcol) = __halves2bfloat162(l0, l1);
                } else {
                    *reinterpret_cast<float2*>(Yout + ro * ldy + gcol) = make_float2(v0, v1);
                }
            }
        }
    }
}

// ---------------------------------------------------------------------------
// Residual + LayerNorm (one warp per 512-col row)
// ---------------------------------------------------------------------------
template<int RES_SPLIT, int OUT_SPLIT>
__global__ __launch_bounds__(256)
void ln_kernel(const float* __restrict__ resf,
               const __nv_bfloat16* __restrict__ resh, const __nv_bfloat16* __restrict__ resl,
               const float* __restrict__ Y,
               const float* __restrict__ g, const float* __restrict__ b,
               float* __restrict__ outf, int ldout, int coloff,
               __nv_bfloat16* __restrict__ oh, __nv_bfloat16* __restrict__ ol)
{
    const int w = threadIdx.x >> 5, lane = threadIdx.x & 31;
    const size_t row = (size_t)blockIdx.x * 8 + w;
    const size_t rb = row * EDIM;

    float v[16];
    #pragma unroll
    for (int j = 0; j < 16; j++) {
        const int c = j * 32 + lane;
        const float r = RES_SPLIT
            ? (__bfloat162float(resh[rb + c]) + __bfloat162float(resl[rb + c]))
            : resf[rb + c];
        v[j] = Y[rb + c] + r;
    }
    float s = 0.f;
    #pragma unroll
    for (int j = 0; j < 16; j++) s += v[j];
    #pragma unroll
    for (int o = 16; o > 0; o >>= 1) s += __shfl_xor_sync(0xffffffffu, s, o);
    const float mean = s * (1.0f / EDIM);
    float q = 0.f;
    #pragma unroll
    for (int j = 0; j < 16; j++) { const float d = v[j] - mean; q += d * d; }
    #pragma unroll
    for (int o = 16; o > 0; o >>= 1) q += __shfl_xor_sync(0xffffffffu, q, o);
    const float rs = rsqrtf(q * (1.0f / EDIM) + LN_EPS);

    #pragma unroll
    for (int j = 0; j < 16; j++) {
        const int c = j * 32 + lane;
        const float o = (v[j] - mean) * rs * g[c] + b[c];
        if (OUT_SPLIT) {
            const __nv_bfloat16 h = __float2bfloat16(o);
            oh[rb + c] = h;
            ol[rb + c] = __float2bfloat16(o - __bfloat162float(h));
        } else {
            outf[row * ldout + coloff + c] = o;
        }
    }
}

// fp32 -> bf16 (hi, lo) split, float4-vectorized
__global__ void split_kernel(const float* __restrict__ src,
                             __nv_bfloat16* __restrict__ h, __nv_bfloat16* __restrict__ l, int n4)
{
    const int i = blockIdx.x * blockDim.x + threadIdx.x;
    if (i >= n4) return;
    const float4 v = reinterpret_cast<const float4*>(src)[i];
    const __nv_bfloat16 hx = __float2bfloat16(v.x), hy = __float2bfloat16(v.y);
    const __nv_bfloat16 hz = __float2bfloat16(v.z), hw = __float2bfloat16(v.w);
    const __nv_bfloat16 lx = __float2bfloat16(v.x - __bfloat162float(hx));
    const __nv_bfloat16 ly = __float2bfloat16(v.y - __bfloat162float(hy));
    const __nv_bfloat16 lz = __float2bfloat16(v.z - __bfloat162float(hz));
    const __nv_bfloat16 lw = __float2bfloat16(v.w - __bfloat162float(hw));
    reinterpret_cast<__nv_bfloat162*>(h)[2 * i + 0] = __halves2bfloat162(hx, hy);
    reinterpret_cast<__nv_bfloat162*>(h)[2 * i + 1] = __halves2bfloat162(hz, hw);
    reinterpret_cast<__nv_bfloat162*>(l)[2 * i + 0] = __halves2bfloat162(lx, ly);
    reinterpret_cast<__nv_bfloat162*>(l)[2 * i + 1] = __halves2bfloat162(lz, lw);
}

// ---------------------------------------------------------------------------
// Wvo[j,m] = sum_k Wo[j,k] * Wv[k,m]  (512^3, one-shot)
// ---------------------------------------------------------------------------
__global__ void fuse_w_kernel(const float* __restrict__ Wo,
                              const float* __restrict__ Wv,
                              float* __restrict__ Wvo)
{
    __shared__ float As[32][33];
    __shared__ float Bs[32][33];
    const int tx = threadIdx.x, ty = threadIdx.y;
    const int j0 = blockIdx.y * 32, m0 = blockIdx.x * 32;
    float a00 = 0.f, a01 = 0.f, a10 = 0.f, a11 = 0.f;

    for (int k0 = 0; k0 < 512; k0 += 32) {
        for (int idx = ty * 16 + tx; idx < 1024; idx += 256) {
            const int r = idx >> 5, c = idx & 31;
            As[r][c] = Wo[(j0 + r) * 512 + k0 + c];
            Bs[r][c] = Wv[(k0 + r) * 512 + m0 + c];
        }
        __syncthreads();
        #pragma unroll
        for (int kk = 0; kk < 32; kk++) {
            const float x0 = As[ty][kk], x1 = As[ty + 16][kk];
            const float y0 = Bs[kk][tx], y1 = Bs[kk][tx + 16];
            a00 += x0 * y0; a01 += x0 * y1;
            a10 += x1 * y0; a11 += x1 * y1;
        }
        __syncthreads();
    }
    Wvo[(j0 + ty)      * 512 + m0 + tx]      = a00;
    Wvo[(j0 + ty)      * 512 + m0 + tx + 16] = a01;
    Wvo[(j0 + ty + 16) * 512 + m0 + tx]      = a10;
    Wvo[(j0 + ty + 16) * 512 + m0 + tx + 16] = a11;
}

__global__ void bvo_kernel(const float* __restrict__ Wo,
                           const float* __restrict__ bv,
                           const float* __restrict__ bo,
                           float* __restrict__ bvo)
{
    const int warp = (blockIdx.x * blockDim.x + threadIdx.x) >> 5;
    const int lane = threadIdx.x & 31;
    if (warp >= 512) return;
    float s = 0.f;
    for (int k = lane; k < 512; k += 32) s += Wo[warp * 512 + k] * bv[k];
    #pragma unroll
    for (int off = 16; off > 0; off >>= 1) s += __shfl_xor_sync(0xffffffffu, s, off);
    if (lane == 0) bvo[warp] = s + bo[warp];
}

// ---------------------------------------------------------------------------
extern "C" void kernel_launch(void* const* d_in, const int* in_sizes, int n_in,
                              void* d_out, int out_size)
{
    const float* dna = (const float*)d_in[0];
    const float* mol = (const float*)d_in[1];
    const float* in_w[2]  = {(const float*)d_in[2],  (const float*)d_in[6]};
    const float* in_b[2]  = {(const float*)d_in[3],  (const float*)d_in[7]};
    const float* out_w[2] = {(const float*)d_in[4],  (const float*)d_in[8]};
    const float* out_b[2] = {(const float*)d_in[5],  (const float*)d_in[9]};
    const float* lnA_g[2] = {(const float*)d_in[10], (const float*)d_in[12]};
    const float* lnA_b[2] = {(const float*)d_in[11], (const float*)d_in[13]};
    const float* lnC_g[2] = {(const float*)d_in[14], (const float*)d_in[16]};
    const float* lnC_b[2] = {(const float*)d_in[15], (const float*)d_in[17]};
    const float* w1[2] = {(const float*)d_in[18], (const float*)d_in[22]};
    const float* b1[2] = {(const float*)d_in[19], (const float*)d_in[23]};
    const float* w2[2] = {(const float*)d_in[20], (const float*)d_in[24]};
    const float* b2[2] = {(const float*)d_in[21], (const float*)d_in[25]};
    float* out = (float*)d_out;

    float *Wf, *bvo, *Y;
    __nv_bfloat16 *wh, *wl, *xh, *xl, *x1h, *x1l, *hh, *hl;
    cudaGetSymbolAddress((void**)&Wf,  g_Wf);
    cudaGetSymbolAddress((void**)&bvo, g_bvo);
    cudaGetSymbolAddress((void**)&Y,   g_Y);
    cudaGetSymbolAddress((void**)&wh,  g_wh);
    cudaGetSymbolAddress((void**)&wl,  g_wl);
    cudaGetSymbolAddress((void**)&xh,  g_xh);
    cudaGetSymbolAddress((void**)&xl,  g_xl);
    cudaGetSymbolAddress((void**)&x1h, g_x1h);
    cudaGetSymbolAddress((void**)&x1l, g_x1l);
    cudaGetSymbolAddress((void**)&hh,  g_hh);
    cudaGetSymbolAddress((void**)&hl,  g_hl);

    cudaFuncSetAttribute(gemm_mma<0>, cudaFuncAttributeMaxDynamicSharedMemorySize, DYN_SMEM);
    cudaFuncSetAttribute(gemm_mma<1>, cudaFuncAttributeMaxDynamicSharedMemorySize, DYN_SMEM);

    // ---- prologue: input/weight splits, W fusion ----
    split_kernel<<<MN / 4 / 256, 256>>>(dna, xh, xl, MN / 4);
    split_kernel<<<MN / 4 / 256, 256>>>(mol, xh + MN, xl + MN, MN / 4);
    for (int s = 0; s < 2; s++) {
        fuse_w_kernel<<<dim3(16, 16), dim3(16, 16)>>>(out_w[s], in_w[s] + 2 * EDIM * EDIM,
                                                      Wf + (size_t)s * EDIM * EDIM);
        bvo_kernel<<<64, 256>>>(out_w[s], in_b[s] + 2 * EDIM, out_b[s], bvo + s * EDIM);
        split_kernel<<<(EDIM * EDIM / 4 + 255) / 256, 256>>>(
            Wf + (size_t)s * EDIM * EDIM, wh + s * WSTRIDE + WOFF_VO, wl + s * WSTRIDE + WOFF_VO,
            EDIM * EDIM / 4);
        split_kernel<<<(HDIM * EDIM / 4 + 255) / 256, 256>>>(
            w1[s], wh + s * WSTRIDE + WOFF_W1, wl + s * WSTRIDE + WOFF_W1, HDIM * EDIM / 4);
        split_kernel<<<(EDIM * HDIM / 4 + 255) / 256, 256>>>(
            w2[s], wh + s * WSTRIDE + WOFF_W2, wl + s * WSTRIDE + WOFF_W2, EDIM * HDIM / 4);
    }

    // ---- main pipeline per stream ----
    for (int s = 0; s < 2; s++) {
        const __nv_bfloat16* kvh = xh + (s == 0 ? MN : 0);   // s0 attends over mol, s1 over dna
        const __nv_bfloat16* kvl = xl + (s == 0 ? MN : 0);
        const float* xres = (s == 0) ? dna : mol;

        // A: Y = kv @ Wvo^T + bvo
        gemm_mma<0><<<dim3(EDIM / BN, MROWS / BM), NTHR, DYN_SMEM>>>(
            kvh, kvl, EDIM, wh + s * WSTRIDE + WOFF_VO, wl + s * WSTRIDE + WOFF_VO, EDIM,
            EDIM, bvo + s * EDIM, Y, EDIM, nullptr, nullptr, 0);
        // X1 = LN(x + Y) -> bf16 hi/lo
        ln_kernel<0, 1><<<MROWS / 8, 256>>>(
            xres, nullptr, nullptr, Y, lnA_g[s], lnA_b[s],
            nullptr, 0, 0, x1h + (size_t)s * MN, x1l + (size_t)s * MN);
        // B: H = relu(X1 @ W1^T + b1) -> bf16 hi/lo
        gemm_mma<1><<<dim3(HDIM / BN, MROWS / BM), NTHR, DYN_SMEM>>>(
            x1h + (size_t)s * MN, x1l + (size_t)s * MN, EDIM,
            wh + s * WSTRIDE + WOFF_W1, wl + s * WSTRIDE + WOFF_W1, EDIM,
            EDIM, b1[s], nullptr, 0, hh + (size_t)s * MH, hl + (size_t)s * MH, HDIM);
        // C: Y = H @ W2^T + b2
        gemm_mma<0><<<dim3(EDIM / BN, MROWS / BM), NTHR, DYN_SMEM>>>(
            hh + (size_t)s * MH, hl + (size_t)s * MH, HDIM,
            wh + s * WSTRIDE + WOFF_W2, wl + s * WSTRIDE + WOFF_W2, HDIM,
            HDIM, b2[s], Y, EDIM, nullptr, nullptr, 0);
        // out half = LN(X1 + Y)
        ln_kernel<1, 0><<<MROWS / 8, 256>>>(
            nullptr, x1h + (size_t)s * MN, x1l + (size_t)s * MN, Y, lnC_g[s], lnC_b[s],
            out, 2 * EDIM, s * EDIM, nullptr, nullptr);
    }
}

// round 6
// speedup vs baseline: 3.0657x; 1.2283x over previous
#include <cuda_runtime.h>
#include <cuda_bf16.h>
#include <cstdint>

#define EDIM   512
#define MROWS  32768
#define HDIM   1024
#define LN_EPS 1e-5f

// ---------------- mma.sync GEMM tiling ----------------
#define BM 128
#define BN 128
#define BK 32
#define NTHR 256

#define ROWB   80                    // smem row stride (bank-rotation, conflict-free ldmatrix)
#define ARRB   (128 * ROWB)
#define STAGEB (4 * ARRB)            // Ah, Al, Bh, Bl
#define DYN_SMEM (2 * STAGEB)        // 81920

#define MN (MROWS * EDIM)
#define MH (MROWS * HDIM)
#define WOFF_VO 0
#define WOFF_W1 262144
#define WOFF_W2 786432
#define WSTRIDE 1310720

// ---------------- device scratch ----------------
__device__ float          g_bvo[2 * EDIM];
__device__ __nv_bfloat16  g_wh [2 * WSTRIDE];
__device__ __nv_bfloat16  g_wl [2 * WSTRIDE];
__device__ __nv_bfloat16  g_xh [2 * MN];
__device__ __nv_bfloat16  g_xl [2 * MN];
__device__ __nv_bfloat16  g_x1h[2 * MN];
__device__ __nv_bfloat16  g_x1l[2 * MN];
__device__ __nv_bfloat16  g_hh [2l * MH];
__device__ __nv_bfloat16  g_hl [2l * MH];
__device__ float          g_Y  [2 * MN];

// ---------------- PTX helpers ----------------
__device__ __forceinline__ uint32_t smem_u32(const void* p) {
    uint32_t a;
    asm("{ .reg .u64 t; cvta.to.shared.u64 t, %1; cvt.u32.u64 %0, t; }" : "=r"(a) : "l"(p));
    return a;
}
__device__ __forceinline__ void ldsm4(uint32_t* r, uint32_t addr) {
    asm volatile("ldmatrix.sync.aligned.x4.m8n8.shared.b16 {%0,%1,%2,%3}, [%4];"
                 : "=r"(r[0]), "=r"(r[1]), "=r"(r[2]), "=r"(r[3]) : "r"(addr));
}
__device__ __forceinline__ void mma_bf16(float* c, const uint32_t* a, const uint32_t* b) {
    asm volatile(
        "mma.sync.aligned.m16n8k16.row.col.f32.bf16.bf16.f32 "
        "{%0,%1,%2,%3}, {%4,%5,%6,%7}, {%8,%9}, {%0,%1,%2,%3};"
        : "+f"(c[0]), "+f"(c[1]), "+f"(c[2]), "+f"(c[3])
        : "r"(a[0]), "r"(a[1]), "r"(a[2]), "r"(a[3]), "r"(b[0]), "r"(b[1]));
}
__device__ __forceinline__ void cp16(uint32_t dst, const void* src) {
    asm volatile("cp.async.cg.shared.global [%0], [%1], 16;" :: "r"(dst), "l"(src) : "memory");
}
__device__ __forceinline__ void split_write(__nv_bfloat16* h, __nv_bfloat16* l, size_t i, float v) {
    const __nv_bfloat16 hv = __float2bfloat16(v);
    h[i] = hv;
    l[i] = __float2bfloat16(v - __bfloat162float(hv));
}

// ---------------------------------------------------------------------------
struct GArgs {
    const __nv_bfloat16 *Ah, *Al, *Bh, *Bl;
    const float* bias;
    float* Y;
    __nv_bfloat16 *Oh, *Ol;
};

// GEMM: C[row0:BM, ncol0:BN] = A @ B^T (K-major bf16 hi/lo); 3-term fp32-faithful.
// EPI 0: Y = acc + bias (fp32).  EPI 1: Oh/Ol = split(relu(acc + bias)).
template<int EPI>
__global__ __launch_bounds__(NTHR, 2)
void gemm_mma(GArgs ga0, GArgs ga1, int lda, int ldb, int K, int ldy, int ldo)
{
    extern __shared__ char smraw[];
    const uint32_t sb = smem_u32(smraw);
    const GArgs ga = blockIdx.z ? ga1 : ga0;

    const int t  = threadIdx.x;
    const int l  = t & 31;
    const int w  = t >> 5;
    const int wr = w >> 2;
    const int wn = w & 3;
    const int ncol0 = blockIdx.x * BN;
    const int row0  = blockIdx.y * BM;

    // per-thread cp.async plan: 8 x 16B per chunk
    const __nv_bfloat16* srcbase[8];
    uint32_t dstoff[8];
    {
        const __nv_bfloat16* srcs[4] = {ga.Ah, ga.Al, ga.Bh, ga.Bl};
        #pragma unroll
        for (int j = 0; j < 8; j++) {
            const int u   = t + j * NTHR;
            const int arr = u >> 9;
            const int i   = u & 511;
            const int row = i >> 2;
            const int c   = i & 3;
            const int gr0 = (arr < 2) ? row0 : ncol0;
            const int ld  = (arr < 2) ? lda : ldb;
            srcbase[j] = srcs[arr] + (size_t)(gr0 + row) * ld + c * 8;
            dstoff[j]  = arr * ARRB + row * ROWB + c * 16;
        }
    }

    float acc[4][4][4];
    #pragma unroll
    for (int mt = 0; mt < 4; mt++)
        #pragma unroll
        for (int nt = 0; nt < 4; nt++)
            #pragma unroll
            for (int e = 0; e < 4; e++) acc[mt][nt][e] = 0.f;

    const int nch = K / BK;

    #pragma unroll
    for (int s = 0; s < 2; s++) {
        const int kt = s * BK;
        #pragma unroll
        for (int j = 0; j < 8; j++) cp16(sb + s * STAGEB + dstoff[j], srcbase[j] + kt);
        asm volatile("cp.async.commit_group;" ::: "memory");
    }

    const uint32_t a_row  = (uint32_t)(wr * 64 + (l & 15)) * ROWB;
    const uint32_t a_chk  = (uint32_t)(l >> 4) << 4;
    const uint32_t b_row0 = (uint32_t)(wn * 32 + (l >> 4) * 8 + (l & 7)) * ROWB;
    const uint32_t b_chk  = (uint32_t)((l >> 3) & 1) << 4;

    for (int ch = 0; ch < nch; ch++) {
        if (ch == nch - 1) asm volatile("cp.async.wait_group 0;" ::: "memory");
        else               asm volatile("cp.async.wait_group 1;" ::: "memory");
        __syncthreads();

        const uint32_t sA = sb + (ch & 1) * STAGEB;
        #pragma unroll
        for (int ks = 0; ks < 2; ks++) {
            const uint32_t koff = (uint32_t)(ks * 2) << 4;
            uint32_t a_h[4][4], a_l[4][4];
            #pragma unroll
            for (int mt = 0; mt < 4; mt++) {
                const uint32_t ad = sA + a_row + (uint32_t)(mt * 16) * ROWB + koff + a_chk;
                ldsm4(a_h[mt], ad);
                ldsm4(a_l[mt], ad + ARRB);
            }
            uint32_t b_h[2][4], b_l[2][4];
            #pragma unroll
            for (int p = 0; p < 2; p++) {
                const uint32_t bd = sA + 2 * ARRB + b_row0 + (uint32_t)(p * 16) * ROWB + koff + b_chk;
                ldsm4(b_h[p], bd);
                ldsm4(b_l[p], bd + ARRB);
            }
            #pragma unroll
            for (int mt = 0; mt < 4; mt++)
                #pragma unroll
                for (int nt = 0; nt < 4; nt++) {
                    float* c = acc[mt][nt];
                    const uint32_t* bh = &b_h[nt >> 1][(nt & 1) * 2];
                    const uint32_t* bl = &b_l[nt >> 1][(nt & 1) * 2];
                    mma_bf16(c, a_h[mt], bh);
                    mma_bf16(c, a_h[mt], bl);
                    mma_bf16(c, a_l[mt], bh);
                }
        }
        __syncthreads();
        if (ch + 2 < nch) {
            const int kt = (ch + 2) * BK;
            const uint32_t sD = sb + (ch & 1) * STAGEB;
            #pragma unroll
            for (int j = 0; j < 8; j++) cp16(sD + dstoff[j], srcbase[j] + kt);
        }
        asm volatile("cp.async.commit_group;" ::: "memory");
    }

    // epilogue
    #pragma unroll
    for (int mt = 0; mt < 4; mt++) {
        #pragma unroll
        for (int nt = 0; nt < 4; nt++) {
            const int r_base = row0 + wr * 64 + mt * 16 + (l >> 2);
            const int gcol   = ncol0 + wn * 32 + nt * 8 + (l & 3) * 2;
            const float b0v = __ldg(ga.bias + gcol);
            const float b1v = __ldg(ga.bias + gcol + 1);
            #pragma unroll
            for (int h = 0; h < 2; h++) {
                float v0 = acc[mt][nt][h * 2 + 0] + b0v;
                float v1 = acc[mt][nt][h * 2 + 1] + b1v;
                const size_t ro = (size_t)(r_base + h * 8);
                if (EPI == 1) {
                    v0 = fmaxf(v0, 0.f);
                    v1 = fmaxf(v1, 0.f);
                    const __nv_bfloat16 h0 = __float2bfloat16(v0);
                    const __nv_bfloat16 h1 = __float2bfloat16(v1);
                    const __nv_bfloat16 l0 = __float2bfloat16(v0 - __bfloat162float(h0));
                    const __nv_bfloat16 l1 = __float2bfloat16(v1 - __bfloat162float(h1));
                    *reinterpret_cast<__nv_bfloat162*>(ga.Oh + ro * ldo + gcol) = __halves2bfloat162(h0, h1);
                    *reinterpret_cast<__nv_bfloat162*>(ga.Ol + ro * ldo + gcol) = __halves2bfloat162(l0, l1);
                } else {
                    *reinterpret_cast<float2*>(ga.Y + ro * ldy + gcol) = make_float2(v0, v1);
                }
            }
        }
    }
}

// ---------------------------------------------------------------------------
struct LArgs {
    const float* resf;
    const __nv_bfloat16 *resh, *resl;
    const float* Y;
    const float *g, *b;
    float* outf;
    int coloff;
    __nv_bfloat16 *oh, *ol;
};

// Residual + LayerNorm (one warp per 512-col row), both streams via blockIdx.z
template<int RES_SPLIT, int OUT_SPLIT>
__global__ __launch_bounds__(256)
void ln_kernel(LArgs la0, LArgs la1, int ldout)
{
    const LArgs la = blockIdx.z ? la1 : la0;
    const int w = threadIdx.x >> 5, lane = threadIdx.x & 31;
    const size_t row = (size_t)blockIdx.x * 8 + w;
    const size_t rb = row * EDIM;

    float v[16];
    #pragma unroll
    for (int j = 0; j < 16; j++) {
        const int c = j * 32 + lane;
        const float r = RES_SPLIT
            ? (__bfloat162float(la.resh[rb + c]) + __bfloat162float(la.resl[rb + c]))
            : la.resf[rb + c];
        v[j] = la.Y[rb + c] + r;
    }
    float s = 0.f;
    #pragma unroll
    for (int j = 0; j < 16; j++) s += v[j];
    #pragma unroll
    for (int o = 16; o > 0; o >>= 1) s += __shfl_xor_sync(0xffffffffu, s, o);
    const float mean = s * (1.0f / EDIM);
    float q = 0.f;
    #pragma unroll
    for (int j = 0; j < 16; j++) { const float d = v[j] - mean; q += d * d; }
    #pragma unroll
    for (int o = 16; o > 0; o >>= 1) q += __shfl_xor_sync(0xffffffffu, q, o);
    const float rs = rsqrtf(q * (1.0f / EDIM) + LN_EPS);

    #pragma unroll
    for (int j = 0; j < 16; j++) {
        const int c = j * 32 + lane;
        const float o = (v[j] - mean) * rs * la.g[c] + la.b[c];
        if (OUT_SPLIT) split_write(la.oh, la.ol, rb + c, o);
        else la.outf[row * ldout + la.coloff + c] = o;
    }
}

// ---------------------------------------------------------------------------
// input split: z=0 -> src0, z=1 -> src1
__global__ void split_in_kernel(const float* __restrict__ src0, const float* __restrict__ src1,
                                __nv_bfloat16* __restrict__ h, __nv_bfloat16* __restrict__ l, int n4)
{
    const int i = blockIdx.x * blockDim.x + threadIdx.x;
    if (i >= n4) return;
    const float* src = blockIdx.z ? src1 : src0;
    const size_t base = (size_t)blockIdx.z * n4;
    const float4 v = reinterpret_cast<const float4*>(src)[i];
    const size_t o = (base + i) * 4;
    split_write(h, l, o + 0, v.x);
    split_write(h, l, o + 1, v.y);
    split_write(h, l, o + 2, v.z);
    split_write(h, l, o + 3, v.w);
}

// 4-way weight split (w1/w2 for both streams), selected by blockIdx.y
struct SplitSet { const float* src; __nv_bfloat16 *h, *l; };
__global__ void splitw_kernel(SplitSet s0, SplitSet s1, SplitSet s2, SplitSet s3, int n4)
{
    const int i = blockIdx.x * blockDim.x + threadIdx.x;
    if (i >= n4) return;
    SplitSet ss = s0;
    if (blockIdx.y == 1) ss = s1;
    else if (blockIdx.y == 2) ss = s2;
    else if (blockIdx.y == 3) ss = s3;
    const float4 v = reinterpret_cast<const float4*>(ss.src)[i];
    const size_t o = (size_t)i * 4;
    split_write(ss.h, ss.l, o + 0, v.x);
    split_write(ss.h, ss.l, o + 1, v.y);
    split_write(ss.h, ss.l, o + 2, v.z);
    split_write(ss.h, ss.l, o + 3, v.w);
}

// ---------------------------------------------------------------------------
// Wvo = Wo @ Wv (512^3), written directly as bf16 hi/lo; x==16 slice does bvo.
// grid (17, 16, 2), block (16, 16)
struct FuseArgs { const float *Wo, *Wv, *bv, *bo; __nv_bfloat16 *wh, *wl; float* bvo; };
__global__ void fuse_w_kernel(FuseArgs f0, FuseArgs f1)
{
    const FuseArgs f = blockIdx.z ? f1 : f0;
    const int tx = threadIdx.x, ty = threadIdx.y;
    const int j0 = blockIdx.y * 32;

    if (blockIdx.x == 16) {     // bvo slice: 32 rows, 8 lanes per row
        const int tid  = ty * 16 + tx;
        const int warp = tid >> 5, lane = tid & 31;
        const int row  = j0 + warp * 4 + (lane >> 3);
        const int sub  = lane & 7;
        float s = 0.f;
        for (int k = sub; k < 512; k += 8) s += f.Wo[row * 512 + k] * f.bv[k];
        #pragma unroll
        for (int o = 4; o > 0; o >>= 1) s += __shfl_xor_sync(0xffffffffu, s, o);
        if (sub == 0) f.bvo[row] = s + f.bo[row];
        return;
    }

    __shared__ float As[32][33];
    __shared__ float Bs[32][33];
    const int m0 = blockIdx.x * 32;
    float a00 = 0.f, a01 = 0.f, a10 = 0.f, a11 = 0.f;

    for (int k0 = 0; k0 < 512; k0 += 32) {
        for (int idx = ty * 16 + tx; idx < 1024; idx += 256) {
            const int r = idx >> 5, c = idx & 31;
            As[r][c] = f.Wo[(j0 + r) * 512 + k0 + c];
            Bs[r][c] = f.Wv[(k0 + r) * 512 + m0 + c];
        }
        __syncthreads();
        #pragma unroll
        for (int kk = 0; kk < 32; kk++) {
            const float x0 = As[ty][kk], x1 = As[ty + 16][kk];
            const float y0 = Bs[kk][tx], y1 = Bs[kk][tx + 16];
            a00 += x0 * y0; a01 += x0 * y1;
            a10 += x1 * y0; a11 += x1 * y1;
        }
        __syncthreads();
    }
    split_write(f.wh, f.wl, (size_t)(j0 + ty)      * 512 + m0 + tx,      a00);
    split_write(f.wh, f.wl, (size_t)(j0 + ty)      * 512 + m0 + tx + 16, a01);
    split_write(f.wh, f.wl, (size_t)(j0 + ty + 16) * 512 + m0 + tx,      a10);
    split_write(f.wh, f.wl, (size_t)(j0 + ty + 16) * 512 + m0 + tx + 16, a11);
}

// ---------------------------------------------------------------------------
extern "C" void kernel_launch(void* const* d_in, const int* in_sizes, int n_in,
                              void* d_out, int out_size)
{
    const float* dna = (const float*)d_in[0];
    const float* mol = (const float*)d_in[1];
    const float* in_w[2]  = {(const float*)d_in[2],  (const float*)d_in[6]};
    const float* in_b[2]  = {(const float*)d_in[3],  (const float*)d_in[7]};
    const float* out_w[2] = {(const float*)d_in[4],  (const float*)d_in[8]};
    const float* out_b[2] = {(const float*)d_in[5],  (const float*)d_in[9]};
    const float* lnA_g[2] = {(const float*)d_in[10], (const float*)d_in[12]};
    const float* lnA_b[2] = {(const float*)d_in[11], (const float*)d_in[13]};
    const float* lnC_g[2] = {(const float*)d_in[14], (const float*)d_in[16]};
    const float* lnC_b[2] = {(const float*)d_in[15], (const float*)d_in[17]};
    const float* w1[2] = {(const float*)d_in[18], (const float*)d_in[22]};
    const float* b1[2] = {(const float*)d_in[19], (const float*)d_in[23]};
    const float* w2[2] = {(const float*)d_in[20], (const float*)d_in[24]};
    const float* b2[2] = {(const float*)d_in[21], (const float*)d_in[25]};
    float* out = (float*)d_out;

    float *bvo, *Y;
    __nv_bfloat16 *wh, *wl, *xh, *xl, *x1h, *x1l, *hh, *hl;
    cudaGetSymbolAddress((void**)&bvo, g_bvo);
    cudaGetSymbolAddress((void**)&Y,   g_Y);
    cudaGetSymbolAddress((void**)&wh,  g_wh);
    cudaGetSymbolAddress((void**)&wl,  g_wl);
    cudaGetSymbolAddress((void**)&xh,  g_xh);
    cudaGetSymbolAddress((void**)&xl,  g_xl);
    cudaGetSymbolAddress((void**)&x1h, g_x1h);
    cudaGetSymbolAddress((void**)&x1l, g_x1l);
    cudaGetSymbolAddress((void**)&hh,  g_hh);
    cudaGetSymbolAddress((void**)&hl,  g_hl);

    cudaFuncSetAttribute(gemm_mma<0>, cudaFuncAttributeMaxDynamicSharedMemorySize, DYN_SMEM);
    cudaFuncSetAttribute(gemm_mma<1>, cudaFuncAttributeMaxDynamicSharedMemorySize, DYN_SMEM);

    // ---- prologue (3 launches) ----
    // L0: input splits (dna -> [0,MN), mol -> [MN,2MN))
    split_in_kernel<<<dim3(MN / 4 / 256, 1, 2), 256>>>(dna, mol, xh, xl, MN / 4);
    // L1: w1/w2 splits for both streams
    {
        SplitSet s0 = {w1[0], wh + 0 * WSTRIDE + WOFF_W1, wl + 0 * WSTRIDE + WOFF_W1};
        SplitSet s1 = {w2[0], wh + 0 * WSTRIDE + WOFF_W2, wl + 0 * WSTRIDE + WOFF_W2};
        SplitSet s2 = {w1[1], wh + 1 * WSTRIDE + WOFF_W1, wl + 1 * WSTRIDE + WOFF_W1};
        SplitSet s3 = {w2[1], wh + 1 * WSTRIDE + WOFF_W2, wl + 1 * WSTRIDE + WOFF_W2};
        splitw_kernel<<<dim3(HDIM * EDIM / 4 / 256, 4), 256>>>(s0, s1, s2, s3, HDIM * EDIM / 4);
    }
    // L2: Wvo fuse + split + bvo, both streams
    {
        FuseArgs f0 = {out_w[0], in_w[0] + 2 * EDIM * EDIM, in_b[0] + 2 * EDIM, out_b[0],
                       wh + 0 * WSTRIDE + WOFF_VO, wl + 0 * WSTRIDE + WOFF_VO, bvo + 0 * EDIM};
        FuseArgs f1 = {out_w[1], in_w[1] + 2 * EDIM * EDIM, in_b[1] + 2 * EDIM, out_b[1],
                       wh + 1 * WSTRIDE + WOFF_VO, wl + 1 * WSTRIDE + WOFF_VO, bvo + 1 * EDIM};
        fuse_w_kernel<<<dim3(17, 16, 2), dim3(16, 16)>>>(f0, f1);
    }

    // ---- main pipeline (both streams merged via blockIdx.z) ----
    // stream 0 (dna side) attends over mol (xh+MN); stream 1 over dna (xh+0)
    // L3: gemm A -> Y
    {
        GArgs a0 = {xh + MN, xl + MN, wh + 0 * WSTRIDE + WOFF_VO, wl + 0 * WSTRIDE + WOFF_VO,
                    bvo + 0 * EDIM, Y + 0 * MN, nullptr, nullptr};
        GArgs a1 = {xh,      xl,      wh + 1 * WSTRIDE + WOFF_VO, wl + 1 * WSTRIDE + WOFF_VO,
                    bvo + 1 * EDIM, Y + 1 * MN, nullptr, nullptr};
        gemm_mma<0><<<dim3(EDIM / BN, MROWS / BM, 2), NTHR, DYN_SMEM>>>(
            a0, a1, EDIM, EDIM, EDIM, EDIM, 0);
    }
    // L4: ln1 -> x1 (split)
    {
        LArgs l0 = {dna, nullptr, nullptr, Y + 0 * MN, lnA_g[0], lnA_b[0], nullptr, 0, x1h, x1l};
        LArgs l1 = {mol, nullptr, nullptr, Y + 1 * MN, lnA_g[1], lnA_b[1], nullptr, 0, x1h + MN, x1l + MN};
        ln_kernel<0, 1><<<dim3(MROWS / 8, 1, 2), 256>>>(l0, l1, 0);
    }
    // L5: gemm B (FFN up + relu) -> H (split)    [ncu -s 5 captures this]
    {
        GArgs a0 = {x1h, x1l, wh + 0 * WSTRIDE + WOFF_W1, wl + 0 * WSTRIDE + WOFF_W1,
                    b1[0], nullptr, hh, hl};
        GArgs a1 = {x1h + MN, x1l + MN, wh + 1 * WSTRIDE + WOFF_W1, wl + 1 * WSTRIDE + WOFF_W1,
                    b1[1], nullptr, hh + MH, hl + MH};
        gemm_mma<1><<<dim3(HDIM / BN, MROWS / BM, 2), NTHR, DYN_SMEM>>>(
            a0, a1, EDIM, EDIM, EDIM, 0, HDIM);
    }
    // L6: gemm C (FFN down) -> Y
    {
        GArgs a0 = {hh, hl, wh + 0 * WSTRIDE + WOFF_W2, wl + 0 * WSTRIDE + WOFF_W2,
                    b2[0], Y + 0 * MN, nullptr, nullptr};
        GArgs a1 = {hh + MH, hl + MH, wh + 1 * WSTRIDE + WOFF_W2, wl + 1 * WSTRIDE + WOFF_W2,
                    b2[1], Y + 1 * MN, nullptr, nullptr};
        gemm_mma<0><<<dim3(EDIM / BN, MROWS / BM, 2), NTHR, DYN_SMEM>>>(
            a0, a1, HDIM, HDIM, HDIM, EDIM, 0);
    }
    // L7: ln2 -> output halves
    {
        LArgs l0 = {nullptr, x1h, x1l, Y + 0 * MN, lnC_g[0], lnC_b[0], out, 0, nullptr, nullptr};
        LArgs l1 = {nullptr, x1h + MN, x1l + MN, Y + 1 * MN, lnC_g[1], lnC_b[1], out, EDIM, nullptr, nullptr};
        ln_kernel<1, 0><<<dim3(MROWS / 8, 1, 2), 256>>>(l0, l1, 2 * EDIM);
    }
}

// round 7
// speedup vs baseline: 4.0874x; 1.3333x over previous
#include <cuda_runtime.h>
#include <cuda_fp16.h>
#include <cstdint>

#define EDIM   512
#define MROWS  32768
#define HDIM   1024
#define LN_EPS 1e-5f

// ---------------- mma.sync GEMM tiling ----------------
#define BM 128
#define BN 128
#define BK 32
#define NTHR 256

#define ROWB   80                    // smem row stride (bank rotation, conflict-free ldmatrix)
#define ARRB   (128 * ROWB)          // 10240
#define STAGEB (3 * ARRB)            // Ah, Al, Bh  -> 30720
#define NSTAGE 3
#define DYN_SMEM (NSTAGE * STAGEB)   // 92160

#define MN (MROWS * EDIM)
#define MH (MROWS * HDIM)
#define WOFF_VO 0
#define WOFF_W1 262144
#define WOFF_W2 786432
#define WSTRIDE 1310720

// ---------------- device scratch ----------------
__device__ float   g_bvo[2 * EDIM];
__device__ __half  g_wh [2 * WSTRIDE];      // fp16 weights (B operands, single-rounded)
__device__ __half  g_xh [2 * MN];           // fp16 hi of inputs
__device__ __half  g_xl [2 * MN];           // fp16 lo of inputs
__device__ __half  g_x1h[2 * MN];
__device__ __half  g_x1l[2 * MN];
__device__ __half  g_hh [2l * MH];
__device__ __half  g_hl [2l * MH];
__device__ float   g_Y  [2 * MN];

// ---------------- PTX helpers ----------------
__device__ __forceinline__ uint32_t smem_u32(const void* p) {
    uint32_t a;
    asm("{ .reg .u64 t; cvta.to.shared.u64 t, %1; cvt.u32.u64 %0, t; }" : "=r"(a) : "l"(p));
    return a;
}
__device__ __forceinline__ void ldsm4(uint32_t* r, uint32_t addr) {
    asm volatile("ldmatrix.sync.aligned.x4.m8n8.shared.b16 {%0,%1,%2,%3}, [%4];"
                 : "=r"(r[0]), "=r"(r[1]), "=r"(r[2]), "=r"(r[3]) : "r"(addr));
}
__device__ __forceinline__ void mma_f16(float* c, const uint32_t* a, const uint32_t* b) {
    asm volatile(
        "mma.sync.aligned.m16n8k16.row.col.f32.f16.f16.f32 "
        "{%0,%1,%2,%3}, {%4,%5,%6,%7}, {%8,%9}, {%0,%1,%2,%3};"
        : "+f"(c[0]), "+f"(c[1]), "+f"(c[2]), "+f"(c[3])
        : "r"(a[0]), "r"(a[1]), "r"(a[2]), "r"(a[3]), "r"(b[0]), "r"(b[1]));
}
__device__ __forceinline__ void cp16(uint32_t dst, const void* src) {
    asm volatile("cp.async.cg.shared.global [%0], [%1], 16;" :: "r"(dst), "l"(src) : "memory");
}
__device__ __forceinline__ void split_write_h(__half* h, __half* l, size_t i, float v) {
    const __half hv = __float2half_rn(v);
    h[i] = hv;
    l[i] = __float2half_rn(v - __half2float(hv));
}

// ---------------------------------------------------------------------------
struct GArgs {
    const __half *Ah, *Al, *Bh;
    const float* bias;
    float* Y;
    __half *Oh, *Ol;
};

// GEMM: C[row0:BM, ncol0:BN] = (Ah+Al) @ Bh^T (K-major fp16); fp32 accum.
// EPI 0: Y = acc + bias (fp32).  EPI 1: Oh/Ol = split(relu(acc + bias)).
template<int EPI>
__global__ __launch_bounds__(NTHR, 2)
void gemm_mma(GArgs ga0, GArgs ga1, int lda, int ldb, int K, int ldy, int ldo)
{
    extern __shared__ char smraw[];
    const uint32_t sb = smem_u32(smraw);
    const GArgs ga = blockIdx.z ? ga1 : ga0;

    const int t  = threadIdx.x;
    const int l  = t & 31;
    const int w  = t >> 5;
    const int wr = w >> 2;               // 0..1 (M)
    const int wn = w & 3;                // 0..3 (N)
    const int ncol0 = blockIdx.x * BN;   // N fastest -> A tile L2 reuse
    const int row0  = blockIdx.y * BM;

    // cp.async plan: each thread copies 6 x 16B per stage (rows rowA and rowA+64)
    const int rowA = t >> 2;             // 0..63
    const int ce   = (t & 3) * 8;        // element offset (8 halves = 16B)
    const __half* pA  = ga.Ah + (size_t)(row0 + rowA) * lda + ce;
    const __half* pAl = ga.Al + (size_t)(row0 + rowA) * lda + ce;
    const __half* pB  = ga.Bh + (size_t)(ncol0 + rowA) * ldb + ce;
    const uint32_t dbase = (uint32_t)rowA * ROWB + (uint32_t)(t & 3) * 16;

    float acc[4][4][4];
    #pragma unroll
    for (int mt = 0; mt < 4; mt++)
        #pragma unroll
        for (int nt = 0; nt < 4; nt++)
            #pragma unroll
            for (int e = 0; e < 4; e++) acc[mt][nt][e] = 0.f;

    const int nch = K / BK;

    auto fill = [&](int stage, int kt) {
        const uint32_t dst = sb + stage * STAGEB;
        cp16(dst + dbase,                      pA  + kt);
        cp16(dst + 64 * ROWB + dbase,          pA  + (size_t)64 * lda + kt);
        cp16(dst + ARRB + dbase,               pAl + kt);
        cp16(dst + ARRB + 64 * ROWB + dbase,   pAl + (size_t)64 * lda + kt);
        cp16(dst + 2 * ARRB + dbase,           pB  + kt);
        cp16(dst + 2 * ARRB + 64 * ROWB + dbase, pB + (size_t)64 * ldb + kt);
    };

    // prologue: stages 0, 1
    fill(0, 0);
    asm volatile("cp.async.commit_group;" ::: "memory");
    fill(1, BK);
    asm volatile("cp.async.commit_group;" ::: "memory");

    const uint32_t a_row  = (uint32_t)(wr * 64 + (l & 15)) * ROWB;
    const uint32_t a_chk  = (uint32_t)(l >> 4) << 4;
    const uint32_t b_row0 = (uint32_t)(wn * 32 + (l >> 4) * 8 + (l & 7)) * ROWB;
    const uint32_t b_chk  = (uint32_t)((l >> 3) & 1) << 4;

    int st_cur = 0, st_n2 = 2;
    for (int ch = 0; ch < nch; ch++) {
        asm volatile("cp.async.wait_group 1;" ::: "memory");
        __syncthreads();

        if (ch + 2 < nch) fill(st_n2, (ch + 2) * BK);
        asm volatile("cp.async.commit_group;" ::: "memory");

        const uint32_t sA = sb + st_cur * STAGEB;
        #pragma unroll
        for (int ks = 0; ks < 2; ks++) {
            const uint32_t koff = (uint32_t)ks * 32;
            uint32_t b_h[2][4];
            #pragma unroll
            for (int p = 0; p < 2; p++)
                ldsm4(b_h[p], sA + 2 * ARRB + b_row0 + (uint32_t)(p * 16) * ROWB + koff + b_chk);

            uint32_t a[4][4];
            #pragma unroll
            for (int mt = 0; mt < 4; mt++)
                ldsm4(a[mt], sA + a_row + (uint32_t)(mt * 16) * ROWB + koff + a_chk);
            #pragma unroll
            for (int mt = 0; mt < 4; mt++)
                #pragma unroll
                for (int nt = 0; nt < 4; nt++)
                    mma_f16(acc[mt][nt], a[mt], &b_h[nt >> 1][(nt & 1) * 2]);

            #pragma unroll
            for (int mt = 0; mt < 4; mt++)
                ldsm4(a[mt], sA + ARRB + a_row + (uint32_t)(mt * 16) * ROWB + koff + a_chk);
            #pragma unroll
            for (int mt = 0; mt < 4; mt++)
                #pragma unroll
                for (int nt = 0; nt < 4; nt++)
                    mma_f16(acc[mt][nt], a[mt], &b_h[nt >> 1][(nt & 1) * 2]);
        }
        st_cur = (st_cur == 2) ? 0 : st_cur + 1;
        st_n2  = (st_n2  == 2) ? 0 : st_n2  + 1;
    }

    // ---------------- epilogue ----------------
    #pragma unroll
    for (int mt = 0; mt < 4; mt++) {
        #pragma unroll
        for (int nt = 0; nt < 4; nt++) {
            const int r_base = row0 + wr * 64 + mt * 16 + (l >> 2);
            const int gcol   = ncol0 + wn * 32 + nt * 8 + (l & 3) * 2;
            const float b0v = __ldg(ga.bias + gcol);
            const float b1v = __ldg(ga.bias + gcol + 1);
            #pragma unroll
            for (int h = 0; h < 2; h++) {
                float v0 = acc[mt][nt][h * 2 + 0] + b0v;
                float v1 = acc[mt][nt][h * 2 + 1] + b1v;
                const size_t ro = (size_t)(r_base + h * 8);
                if (EPI == 1) {
                    v0 = fmaxf(v0, 0.f);
                    v1 = fmaxf(v1, 0.f);
                    const __half h0 = __float2half_rn(v0);
                    const __half h1 = __float2half_rn(v1);
                    const __half l0 = __float2half_rn(v0 - __half2float(h0));
                    const __half l1 = __float2half_rn(v1 - __half2float(h1));
                    *reinterpret_cast<__half2*>(ga.Oh + ro * ldo + gcol) = __halves2half2(h0, h1);
                    *reinterpret_cast<__half2*>(ga.Ol + ro * ldo + gcol) = __halves2half2(l0, l1);
                } else {
                    *reinterpret_cast<float2*>(ga.Y + ro * ldy + gcol) = make_float2(v0, v1);
                }
            }
        }
    }
}

// ---------------------------------------------------------------------------
struct LArgs {
    const float* resf;
    const __half *resh, *resl;
    const float* Y;
    const float *g, *b;
    float* outf;
    int coloff;
    __half *oh, *ol;
};

// Residual + LayerNorm (one warp per 512-col row), both streams via blockIdx.z
template<int RES_SPLIT, int OUT_SPLIT>
__global__ __launch_bounds__(256)
void ln_kernel(LArgs la0, LArgs la1, int ldout)
{
    const LArgs la = blockIdx.z ? la1 : la0;
    const int w = threadIdx.x >> 5, lane = threadIdx.x & 31;
    const size_t row = (size_t)blockIdx.x * 8 + w;
    const size_t rb = row * EDIM;

    float v[16];
    #pragma unroll
    for (int j = 0; j < 16; j++) {
        const int c = j * 32 + lane;
        const float r = RES_SPLIT
            ? (__half2float(la.resh[rb + c]) + __half2float(la.resl[rb + c]))
            : la.resf[rb + c];
        v[j] = la.Y[rb + c] + r;
    }
    float s = 0.f;
    #pragma unroll
    for (int j = 0; j < 16; j++) s += v[j];
    #pragma unroll
    for (int o = 16; o > 0; o >>= 1) s += __shfl_xor_sync(0xffffffffu, s, o);
    const float mean = s * (1.0f / EDIM);
    float q = 0.f;
    #pragma unroll
    for (int j = 0; j < 16; j++) { const float d = v[j] - mean; q += d * d; }
    #pragma unroll
    for (int o = 16; o > 0; o >>= 1) q += __shfl_xor_sync(0xffffffffu, q, o);
    const float rs = rsqrtf(q * (1.0f / EDIM) + LN_EPS);

    #pragma unroll
    for (int j = 0; j < 16; j++) {
        const int c = j * 32 + lane;
        const float o = (v[j] - mean) * rs * la.g[c] + la.b[c];
        if (OUT_SPLIT) split_write_h(la.oh, la.ol, rb + c, o);
        else la.outf[row * ldout + la.coloff + c] = o;
    }
}

// ---------------------------------------------------------------------------
// input split to fp16 hi/lo: z=0 -> src0, z=1 -> src1
__global__ void split_in_kernel(const float* __restrict__ src0, const float* __restrict__ src1,
                                __half* __restrict__ h, __half* __restrict__ l, int n4)
{
    const int i = blockIdx.x * blockDim.x + threadIdx.x;
    if (i >= n4) return;
    const float* src = blockIdx.z ? src1 : src0;
    const size_t base = (size_t)blockIdx.z * n4;
    const float4 v = reinterpret_cast<const float4*>(src)[i];
    const size_t o = (base + i) * 4;
    split_write_h(h, l, o + 0, v.x);
    split_write_h(h, l, o + 1, v.y);
    split_write_h(h, l, o + 2, v.z);
    split_write_h(h, l, o + 3, v.w);
}

// fp32 -> fp16 single-round weight convert; 4 matrices via blockIdx.y
struct ConvSet { const float* src; __half* dst; };
__global__ void conv_w_kernel(ConvSet s0, ConvSet s1, ConvSet s2, ConvSet s3, int n4)
{
    const int i = blockIdx.x * blockDim.x + threadIdx.x;
    if (i >= n4) return;
    ConvSet ss = s0;
    if (blockIdx.y == 1) ss = s1;
    else if (blockIdx.y == 2) ss = s2;
    else if (blockIdx.y == 3) ss = s3;
    const float4 v = reinterpret_cast<const float4*>(ss.src)[i];
    const size_t o = (size_t)i * 4;
    reinterpret_cast<__half2*>(ss.dst + o)[0] = __floats2half2_rn(v.x, v.y);
    reinterpret_cast<__half2*>(ss.dst + o)[1] = __floats2half2_rn(v.z, v.w);
}

// ---------------------------------------------------------------------------
// Wvo = Wo @ Wv (512^3), written as fp16; blockIdx.x==16 slice computes bvo.
struct FuseArgs { const float *Wo, *Wv, *bv, *bo; __half* wh; float* bvo; };
__global__ void fuse_w_kernel(FuseArgs f0, FuseArgs f1)
{
    const FuseArgs f = blockIdx.z ? f1 : f0;
    const int tx = threadIdx.x, ty = threadIdx.y;
    const int j0 = blockIdx.y * 32;

    if (blockIdx.x == 16) {     // bvo slice
        const int tid  = ty * 16 + tx;
        const int warp = tid >> 5, lane = tid & 31;
        const int row  = j0 + warp * 4 + (lane >> 3);
        const int sub  = lane & 7;
        float s = 0.f;
        for (int k = sub; k < 512; k += 8) s += f.Wo[row * 512 + k] * f.bv[k];
        #pragma unroll
        for (int o = 4; o > 0; o >>= 1) s += __shfl_xor_sync(0xffffffffu, s, o);
        if (sub == 0) f.bvo[row] = s + f.bo[row];
        return;
    }

    __shared__ float As[32][33];
    __shared__ float Bs[32][33];
    const int m0 = blockIdx.x * 32;
    float a00 = 0.f, a01 = 0.f, a10 = 0.f, a11 = 0.f;

    for (int k0 = 0; k0 < 512; k0 += 32) {
        for (int idx = ty * 16 + tx; idx < 1024; idx += 256) {
            const int r = idx >> 5, c = idx & 31;
            As[r][c] = f.Wo[(j0 + r) * 512 + k0 + c];
            Bs[r][c] = f.Wv[(k0 + r) * 512 + m0 + c];
        }
        __syncthreads();
        #pragma unroll
        for (int kk = 0; kk < 32; kk++) {
            const float x0 = As[ty][kk], x1 = As[ty + 16][kk];
            const float y0 = Bs[kk][tx], y1 = Bs[kk][tx + 16];
            a00 += x0 * y0; a01 += x0 * y1;
            a10 += x1 * y0; a11 += x1 * y1;
        }
        __syncthreads();
    }
    f.wh[(size_t)(j0 + ty)      * 512 + m0 + tx]      = __float2half_rn(a00);
    f.wh[(size_t)(j0 + ty)      * 512 + m0 + tx + 16] = __float2half_rn(a01);
    f.wh[(size_t)(j0 + ty + 16) * 512 + m0 + tx]      = __float2half_rn(a10);
    f.wh[(size_t)(j0 + ty + 16) * 512 + m0 + tx + 16] = __float2half_rn(a11);
}

// ---------------------------------------------------------------------------
extern "C" void kernel_launch(void* const* d_in, const int* in_sizes, int n_in,
                              void* d_out, int out_size)
{
    const float* dna = (const float*)d_in[0];
    const float* mol = (const float*)d_in[1];
    const float* in_w[2]  = {(const float*)d_in[2],  (const float*)d_in[6]};
    const float* in_b[2]  = {(const float*)d_in[3],  (const float*)d_in[7]};
    const float* out_w[2] = {(const float*)d_in[4],  (const float*)d_in[8]};
    const float* out_b[2] = {(const float*)d_in[5],  (const float*)d_in[9]};
    const float* lnA_g[2] = {(const float*)d_in[10], (const float*)d_in[12]};
    const float* lnA_b[2] = {(const float*)d_in[11], (const float*)d_in[13]};
    const float* lnC_g[2] = {(const float*)d_in[14], (const float*)d_in[16]};
    const float* lnC_b[2] = {(const float*)d_in[15], (const float*)d_in[17]};
    const float* w1[2] = {(const float*)d_in[18], (const float*)d_in[22]};
    const float* b1[2] = {(const float*)d_in[19], (const float*)d_in[23]};
    const float* w2[2] = {(const float*)d_in[20], (const float*)d_in[24]};
    const float* b2[2] = {(const float*)d_in[21], (const float*)d_in[25]};
    float* out = (float*)d_out;

    float *bvo, *Y;
    __half *wh, *xh, *xl, *x1h, *x1l, *hh, *hl;
    cudaGetSymbolAddress((void**)&bvo, g_bvo);
    cudaGetSymbolAddress((void**)&Y,   g_Y);
    cudaGetSymbolAddress((void**)&wh,  g_wh);
    cudaGetSymbolAddress((void**)&xh,  g_xh);
    cudaGetSymbolAddress((void**)&xl,  g_xl);
    cudaGetSymbolAddress((void**)&x1h, g_x1h);
    cudaGetSymbolAddress((void**)&x1l, g_x1l);
    cudaGetSymbolAddress((void**)&hh,  g_hh);
    cudaGetSymbolAddress((void**)&hl,  g_hl);

    cudaFuncSetAttribute(gemm_mma<0>, cudaFuncAttributeMaxDynamicSharedMemorySize, DYN_SMEM);
    cudaFuncSetAttribute(gemm_mma<1>, cudaFuncAttributeMaxDynamicSharedMemorySize, DYN_SMEM);

    // ---- prologue ----
    // L0: input splits (dna -> [0,MN), mol -> [MN,2MN))
    split_in_kernel<<<dim3(MN / 4 / 256, 1, 2), 256>>>(dna, mol, xh, xl, MN / 4);
    // L1: w1/w2 fp16 converts for both streams
    {
        ConvSet s0 = {w1[0], wh + 0 * WSTRIDE + WOFF_W1};
        ConvSet s1 = {w2[0], wh + 0 * WSTRIDE + WOFF_W2};
        ConvSet s2 = {w1[1], wh + 1 * WSTRIDE + WOFF_W1};
        ConvSet s3 = {w2[1], wh + 1 * WSTRIDE + WOFF_W2};
        conv_w_kernel<<<dim3(HDIM * EDIM / 4 / 256, 4), 256>>>(s0, s1, s2, s3, HDIM * EDIM / 4);
    }
    // L2: Wvo fuse + fp16 + bvo, both streams
    {
        FuseArgs f0 = {out_w[0], in_w[0] + 2 * EDIM * EDIM, in_b[0] + 2 * EDIM, out_b[0],
                       wh + 0 * WSTRIDE + WOFF_VO, bvo + 0 * EDIM};
        FuseArgs f1 = {out_w[1], in_w[1] + 2 * EDIM * EDIM, in_b[1] + 2 * EDIM, out_b[1],
                       wh + 1 * WSTRIDE + WOFF_VO, bvo + 1 * EDIM};
        fuse_w_kernel<<<dim3(17, 16, 2), dim3(16, 16)>>>(f0, f1);
    }

    // ---- main pipeline (both streams merged via blockIdx.z) ----
    // stream 0 (dna side) attends over mol (xh+MN); stream 1 over dna (xh+0)
    // L3: gemm A -> Y
    {
        GArgs a0 = {xh + MN, xl + MN, wh + 0 * WSTRIDE + WOFF_VO, bvo + 0 * EDIM,
                    Y + 0 * MN, nullptr, nullptr};
        GArgs a1 = {xh,      xl,      wh + 1 * WSTRIDE + WOFF_VO, bvo + 1 * EDIM,
                    Y + 1 * MN, nullptr, nullptr};
        gemm_mma<0><<<dim3(EDIM / BN, MROWS / BM, 2), NTHR, DYN_SMEM>>>(
            a0, a1, EDIM, EDIM, EDIM, EDIM, 0);
    }
    // L4: ln1 -> x1 (fp16 split)
    {
        LArgs l0 = {dna, nullptr, nullptr, Y + 0 * MN, lnA_g[0], lnA_b[0], nullptr, 0, x1h, x1l};
        LArgs l1 = {mol, nullptr, nullptr, Y + 1 * MN, lnA_g[1], lnA_b[1], nullptr, 0, x1h + MN, x1l + MN};
        ln_kernel<0, 1><<<dim3(MROWS / 8, 1, 2), 256>>>(l0, l1, 0);
    }
    // L5: gemm B (FFN up + relu) -> H (fp16 split)    [ncu -s 5 captures this]
    {
        GArgs a0 = {x1h, x1l, wh + 0 * WSTRIDE + WOFF_W1, b1[0], nullptr, hh, hl};
        GArgs a1 = {x1h + MN, x1l + MN, wh + 1 * WSTRIDE + WOFF_W1, b1[1], nullptr, hh + MH, hl + MH};
        gemm_mma<1><<<dim3(HDIM / BN, MROWS / BM, 2), NTHR, DYN_SMEM>>>(
            a0, a1, EDIM, EDIM, EDIM, 0, HDIM);
    }
    // L6: gemm C (FFN down) -> Y
    {
        GArgs a0 = {hh, hl, wh + 0 * WSTRIDE + WOFF_W2, b2[0], Y + 0 * MN, nullptr, nullptr};
        GArgs a1 = {hh + MH, hl + MH, wh + 1 * WSTRIDE + WOFF_W2, b2[1], Y + 1 * MN, nullptr, nullptr};
        gemm_mma<0><<<dim3(EDIM / BN, MROWS / BM, 2), NTHR, DYN_SMEM>>>(
            a0, a1, HDIM, HDIM, HDIM, EDIM, 0);
    }
    // L7: ln2 -> output halves
    {
        LArgs l0 = {nullptr, x1h, x1l, Y + 0 * MN, lnC_g[0], lnC_b[0], out, 0, nullptr, nullptr};
        LArgs l1 = {nullptr, x1h + MN, x1l + MN, Y + 1 * MN, lnC_g[1], lnC_b[1], out, EDIM, nullptr, nullptr};
        ln_kernel<1, 0><<<dim3(MROWS / 8, 1, 2), 256>>>(l0, l1, 2 * EDIM);
    }
}

// round 9
// speedup vs baseline: 6.7860x; 1.6602x over previous
#include <cuda_runtime.h>
#include <cuda_fp16.h>
#include <cstdint>

#define EDIM   512
#define MROWS  32768
#define HDIM   1024
#define LN_EPS 1e-5f

// ---------------- mma.sync GEMM tiling ----------------
#define BM 128
#define BN 128
#define BK 64
#define NTHR 256

#define ROWB   144                   // 128B row + 16B pad: bank offset 4/row, conflict-free ldmatrix
#define ARRB   (128 * ROWB)          // 18432
#define STAGEB (2 * ARRB)            // A, B -> 36864
#define NSTAGE 3
#define DYN_SMEM (NSTAGE * STAGEB)   // 110592

#define MN (MROWS * EDIM)
#define MH (MROWS * HDIM)
#define WOFF_VO 0
#define WOFF_W1 262144
#define WOFF_W2 786432
#define WSTRIDE 1310720

// ---------------- device scratch ----------------
__device__ float   g_bvo[2 * EDIM];
__device__ __half  g_wh [2 * WSTRIDE];      // fp16 weights (B operands)
__device__ __half  g_xh [2 * MN];           // fp16 inputs
__device__ __half  g_x1h[2 * MN];           // fp16 x1 (GEMM operand)
__device__ float   g_x1f[2 * MN];           // fp32 x1 (LN2 residual)
__device__ __half  g_hh [2l * MH];          // fp16 relu(FFN up)
__device__ float   g_Y  [2 * MN];           // fp32 GEMM out scratch

// ---------------- PTX helpers ----------------
__device__ __forceinline__ uint32_t smem_u32(const void* p) {
    uint32_t a;
    asm("{ .reg .u64 t; cvta.to.shared.u64 t, %1; cvt.u32.u64 %0, t; }" : "=r"(a) : "l"(p));
    return a;
}
__device__ __forceinline__ void ldsm4(uint32_t* r, uint32_t addr) {
    asm volatile("ldmatrix.sync.aligned.x4.m8n8.shared.b16 {%0,%1,%2,%3}, [%4];"
                 : "=r"(r[0]), "=r"(r[1]), "=r"(r[2]), "=r"(r[3]) : "r"(addr));
}
__device__ __forceinline__ void mma_f16(float* c, const uint32_t* a, const uint32_t* b) {
    asm volatile(
        "mma.sync.aligned.m16n8k16.row.col.f32.f16.f16.f32 "
        "{%0,%1,%2,%3}, {%4,%5,%6,%7}, {%8,%9}, {%0,%1,%2,%3};"
        : "+f"(c[0]), "+f"(c[1]), "+f"(c[2]), "+f"(c[3])
        : "r"(a[0]), "r"(a[1]), "r"(a[2]), "r"(a[3]), "r"(b[0]), "r"(b[1]));
}
__device__ __forceinline__ void cp16(uint32_t dst, const void* src) {
    asm volatile("cp.async.cg.shared.global [%0], [%1], 16;" :: "r"(dst), "l"(src) : "memory");
}

// ---------------------------------------------------------------------------
struct GArgs {
    const __half *Ah, *Bh;
    const float* bias;
    float* Y;
    __half* Oh;
};

// GEMM: C[row0:BM, ncol0:BN] = A @ B^T (K-major fp16, fp32 accum).
// EPI 0: Y = acc + bias (fp32).  EPI 1: Oh = fp16(relu(acc + bias)).
template<int EPI>
__global__ __launch_bounds__(NTHR, 2)
void gemm_mma(GArgs ga0, GArgs ga1, int lda, int ldb, int K, int ldy, int ldo)
{
    extern __shared__ char smraw[];
    const uint32_t sb = smem_u32(smraw);
    const GArgs ga = blockIdx.z ? ga1 : ga0;

    const int t  = threadIdx.x;
    const int l  = t & 31;
    const int w  = t >> 5;
    const int wr = w >> 2;               // 0..1 (M half)
    const int wn = w & 3;                // 0..3 (N quarter)
    const int ncol0 = blockIdx.x * BN;   // N fastest -> A tile L2 reuse
    const int row0  = blockIdx.y * BM;

    // cp.async plan: 8 x 16B per thread per stage (4 A rows + 4 B rows, stride 32)
    const int crow = t >> 3;             // 0..31
    const int cc16 = (t & 7) * 16;       // byte offset within 128B row
    const __half* pA = ga.Ah + (size_t)(row0 + crow) * lda + (t & 7) * 8;
    const __half* pB = ga.Bh + (size_t)(ncol0 + crow) * ldb + (t & 7) * 8;
    const uint32_t dbase = (uint32_t)crow * ROWB + cc16;

    float acc[4][4][4];
    #pragma unroll
    for (int mt = 0; mt < 4; mt++)
        #pragma unroll
        for (int nt = 0; nt < 4; nt++)
            #pragma unroll
            for (int e = 0; e < 4; e++) acc[mt][nt][e] = 0.f;

    const int nch = K / BK;

    auto fill = [&](int stage, int kt) {
        const uint32_t dst = sb + stage * STAGEB;
        #pragma unroll
        for (int j = 0; j < 4; j++) {
            cp16(dst + dbase + (uint32_t)(j * 32) * ROWB,        pA + (size_t)(j * 32) * lda + kt);
            cp16(dst + ARRB + dbase + (uint32_t)(j * 32) * ROWB, pB + (size_t)(j * 32) * ldb + kt);
        }
    };

    fill(0, 0);
    asm volatile("cp.async.commit_group;" ::: "memory");
    fill(1, BK);
    asm volatile("cp.async.commit_group;" ::: "memory");

    const uint32_t a_row  = (uint32_t)(wr * 64 + (l & 15)) * ROWB;
    const uint32_t a_chk  = (uint32_t)(l >> 4) << 4;
    const uint32_t b_row0 = (uint32_t)(wn * 32 + (l >> 4) * 8 + (l & 7)) * ROWB;
    const uint32_t b_chk  = (uint32_t)((l >> 3) & 1) << 4;

    int st_cur = 0, st_n2 = 2;
    for (int ch = 0; ch < nch; ch++) {
        asm volatile("cp.async.wait_group 1;" ::: "memory");
        __syncthreads();

        if (ch + 2 < nch) fill(st_n2, (ch + 2) * BK);
        asm volatile("cp.async.commit_group;" ::: "memory");

        const uint32_t sA = sb + st_cur * STAGEB;
        #pragma unroll
        for (int ks = 0; ks < 4; ks++) {
            const uint32_t koff = (uint32_t)ks * 32;   // 16 halves per k-step
            uint32_t b_h[2][4];
            #pragma unroll
            for (int p = 0; p < 2; p++)
                ldsm4(b_h[p], sA + ARRB + b_row0 + (uint32_t)(p * 16) * ROWB + koff + b_chk);
            uint32_t a[4][4];
            #pragma unroll
            for (int mt = 0; mt < 4; mt++)
                ldsm4(a[mt], sA + a_row + (uint32_t)(mt * 16) * ROWB + koff + a_chk);
            #pragma unroll
            for (int mt = 0; mt < 4; mt++)
                #pragma unroll
                for (int nt = 0; nt < 4; nt++)
                    mma_f16(acc[mt][nt], a[mt], &b_h[nt >> 1][(nt & 1) * 2]);
        }
        st_cur = (st_cur == 2) ? 0 : st_cur + 1;
        st_n2  = (st_n2  == 2) ? 0 : st_n2  + 1;
    }

    // ---------------- epilogue ----------------
    #pragma unroll
    for (int mt = 0; mt < 4; mt++) {
        #pragma unroll
        for (int nt = 0; nt < 4; nt++) {
            const int r_base = row0 + wr * 64 + mt * 16 + (l >> 2);
            const int gcol   = ncol0 + wn * 32 + nt * 8 + (l & 3) * 2;
            const float b0v = __ldg(ga.bias + gcol);
            const float b1v = __ldg(ga.bias + gcol + 1);
            #pragma unroll
            for (int h = 0; h < 2; h++) {
                float v0 = acc[mt][nt][h * 2 + 0] + b0v;
                float v1 = acc[mt][nt][h * 2 + 1] + b1v;
                const size_t ro = (size_t)(r_base + h * 8);
                if (EPI == 1) {
                    v0 = fmaxf(v0, 0.f);
                    v1 = fmaxf(v1, 0.f);
                    *reinterpret_cast<__half2*>(ga.Oh + ro * ldo + gcol) =
                        __floats2half2_rn(v0, v1);
                } else {
                    *reinterpret_cast<float2*>(ga.Y + ro * ldy + gcol) = make_float2(v0, v1);
                }
            }
        }
    }
}

// ---------------------------------------------------------------------------
struct LArgs {
    const float* resf;       // residual (fp32)
    const float* Y;          // GEMM output (fp32)
    const float *g, *b;
    float* x1f;              // MODE 0 out: fp32 copy
    __half* x1h;             // MODE 0 out: fp16 copy
    float* outf;             // MODE 1 out
    int coloff;
};

// MODE 0: x1 = LN(res + Y) -> x1f (fp32) + x1h (fp16)
// MODE 1: out[., coloff:+512] = LN(res + Y)
template<int MODE>
__global__ __launch_bounds__(256)
void ln_kernel(LArgs la0, LArgs la1, int ldout)
{
    const LArgs la = blockIdx.z ? la1 : la0;
    const int w = threadIdx.x >> 5, lane = threadIdx.x & 31;
    const size_t row = (size_t)blockIdx.x * 8 + w;
    const size_t rb = row * EDIM;

    float v[16];
    #pragma unroll
    for (int j = 0; j < 16; j++) {
        const int c = j * 32 + lane;
        v[j] = la.Y[rb + c] + la.resf[rb + c];
    }
    float s = 0.f;
    #pragma unroll
    for (int j = 0; j < 16; j++) s += v[j];
    #pragma unroll
    for (int o = 16; o > 0; o >>= 1) s += __shfl_xor_sync(0xffffffffu, s, o);
    const float mean = s * (1.0f / EDIM);
    float q = 0.f;
    #pragma unroll
    for (int j = 0; j < 16; j++) { const float d = v[j] - mean; q += d * d; }
    #pragma unroll
    for (int o = 16; o > 0; o >>= 1) q += __shfl_xor_sync(0xffffffffu, q, o);
    const float rs = rsqrtf(q * (1.0f / EDIM) + LN_EPS);

    #pragma unroll
    for (int j = 0; j < 16; j++) {
        const int c = j * 32 + lane;
        const float o = (v[j] - mean) * rs * la.g[c] + la.b[c];
        if (MODE == 0) {
            la.x1f[rb + c] = o;
            la.x1h[rb + c] = __float2half_rn(o);
        } else {
            la.outf[row * ldout + la.coloff + c] = o;
        }
    }
}

// ---------------------------------------------------------------------------
// input convert to fp16: z=0 -> src0, z=1 -> src1
__global__ void conv_in_kernel(const float* __restrict__ src0, const float* __restrict__ src1,
                               __half* __restrict__ h, int n4)
{
    const int i = blockIdx.x * blockDim.x + threadIdx.x;
    if (i >= n4) return;
    const float* src = blockIdx.z ? src1 : src0;
    const size_t base = (size_t)blockIdx.z * n4;
    const float4 v = reinterpret_cast<const float4*>(src)[i];
    const size_t o = (base + i) * 4;
    reinterpret_cast<__half2*>(h + o)[0] = __floats2half2_rn(v.x, v.y);
    reinterpret_cast<__half2*>(h + o)[1] = __floats2half2_rn(v.z, v.w);
}

// fp32 -> fp16 weight convert; 4 matrices via blockIdx.y
struct ConvSet { const float* src; __half* dst; };
__global__ void conv_w_kernel(ConvSet s0, ConvSet s1, ConvSet s2, ConvSet s3, int n4)
{
    const int i = blockIdx.x * blockDim.x + threadIdx.x;
    if (i >= n4) return;
    ConvSet ss = s0;
    if (blockIdx.y == 1) ss = s1;
    else if (blockIdx.y == 2) ss = s2;
    else if (blockIdx.y == 3) ss = s3;
    const float4 v = reinterpret_cast<const float4*>(ss.src)[i];
    const size_t o = (size_t)i * 4;
    reinterpret_cast<__half2*>(ss.dst + o)[0] = __floats2half2_rn(v.x, v.y);
    reinterpret_cast<__half2*>(ss.dst + o)[1] = __floats2half2_rn(v.z, v.w);
}

// ---------------------------------------------------------------------------
// Wvo = Wo @ Wv (512^3) -> fp16; blockIdx.x==16 slice computes bvo.
struct FuseArgs { const float *Wo, *Wv, *bv, *bo; __half* wh; float* bvo; };
__global__ void fuse_w_kernel(FuseArgs f0, FuseArgs f1)
{
    const FuseArgs f = blockIdx.z ? f1 : f0;
    const int tx = threadIdx.x, ty = threadIdx.y;
    const int j0 = blockIdx.y * 32;

    if (blockIdx.x == 16) {
        const int tid  = ty * 16 + tx;
        const int warp = tid >> 5, lane = tid & 31;
        const int row  = j0 + warp * 4 + (lane >> 3);
        const int sub  = lane & 7;
        float s = 0.f;
        for (int k = sub; k < 512; k += 8) s += f.Wo[row * 512 + k] * f.bv[k];
        #pragma unroll
        for (int o = 4; o > 0; o >>= 1) s += __shfl_xor_sync(0xffffffffu, s, o);
        if (sub == 0) f.bvo[row] = s + f.bo[row];
        return;
    }

    __shared__ float As[32][33];
    __shared__ float Bs[32][33];
    const int m0 = blockIdx.x * 32;
    float a00 = 0.f, a01 = 0.f, a10 = 0.f, a11 = 0.f;

    for (int k0 = 0; k0 < 512; k0 += 32) {
        for (int idx = ty * 16 + tx; idx < 1024; idx += 256) {
            const int r = idx >> 5, c = idx & 31;
            As[r][c] = f.Wo[(j0 + r) * 512 + k0 + c];
            Bs[r][c] = f.Wv[(k0 + r) * 512 + m0 + c];
        }
        __syncthreads();
        #pragma unroll
        for (int kk = 0; kk < 32; kk++) {
            const float x0 = As[ty][kk], x1 = As[ty + 16][kk];
            const float y0 = Bs[kk][tx], y1 = Bs[kk][tx + 16];
            a00 += x0 * y0; a01 += x0 * y1;
            a10 += x1 * y0; a11 += x1 * y1;
        }
        __syncthreads();
    }
    f.wh[(size_t)(j0 + ty)      * 512 + m0 + tx]      = __float2half_rn(a00);
    f.wh[(size_t)(j0 + ty)      * 512 + m0 + tx + 16] = __float2half_rn(a01);
    f.wh[(size_t)(j0 + ty + 16) * 512 + m0 + tx]      = __float2half_rn(a10);
    f.wh[(size_t)(j0 + ty + 16) * 512 + m0 + tx + 16] = __float2half_rn(a11);
}

// ---------------------------------------------------------------------------
extern "C" void kernel_launch(void* const* d_in, const int* in_sizes, int n_in,
                              void* d_out, int out_size)
{
    const float* dna = (const float*)d_in[0];
    const float* mol = (const float*)d_in[1];
    const float* in_w[2]  = {(const float*)d_in[2],  (const float*)d_in[6]};
    const float* in_b[2]  = {(const float*)d_in[3],  (const float*)d_in[7]};
    const float* out_w[2] = {(const float*)d_in[4],  (const float*)d_in[8]};
    const float* out_b[2] = {(const float*)d_in[5],  (const float*)d_in[9]};
    const float* lnA_g[2] = {(const float*)d_in[10], (const float*)d_in[12]};
    const float* lnA_b[2] = {(const float*)d_in[11], (const float*)d_in[13]};
    const float* lnC_g[2] = {(const float*)d_in[14], (const float*)d_in[16]};
    const float* lnC_b[2] = {(const float*)d_in[15], (const float*)d_in[17]};
    const float* w1[2] = {(const float*)d_in[18], (const float*)d_in[22]};
    const float* b1[2] = {(const float*)d_in[19], (const float*)d_in[23]};
    const float* w2[2] = {(const float*)d_in[20], (const float*)d_in[24]};
    const float* b2[2] = {(const float*)d_in[21], (const float*)d_in[25]};
    float* out = (float*)d_out;

    float *bvo, *Y, *x1f;
    __half *wh, *xh, *x1h, *hh;
    cudaGetSymbolAddress((void**)&bvo, g_bvo);
    cudaGetSymbolAddress((void**)&Y,   g_Y);
    cudaGetSymbolAddress((void**)&x1f, g_x1f);
    cudaGetSymbolAddress((void**)&wh,  g_wh);
    cudaGetSymbolAddress((void**)&xh,  g_xh);
    cudaGetSymbolAddress((void**)&x1h, g_x1h);
    cudaGetSymbolAddress((void**)&hh,  g_hh);

    cudaFuncSetAttribute(gemm_mma<0>, cudaFuncAttributeMaxDynamicSharedMemorySize, DYN_SMEM);
    cudaFuncSetAttribute(gemm_mma<1>, cudaFuncAttributeMaxDynamicSharedMemorySize, DYN_SMEM);

    // ---- prologue ----
    conv_in_kernel<<<dim3(MN / 4 / 256, 1, 2), 256>>>(dna, mol, xh, MN / 4);
    {
        ConvSet s0 = {w1[0], wh + 0 * WSTRIDE + WOFF_W1};
        ConvSet s1 = {w2[0], wh + 0 * WSTRIDE + WOFF_W2};
        ConvSet s2 = {w1[1], wh + 1 * WSTRIDE + WOFF_W1};
        ConvSet s3 = {w2[1], wh + 1 * WSTRIDE + WOFF_W2};
        conv_w_kernel<<<dim3(HDIM * EDIM / 4 / 256, 4), 256>>>(s0, s1, s2, s3, HDIM * EDIM / 4);
    }
    {
        FuseArgs f0 = {out_w[0], in_w[0] + 2 * EDIM * EDIM, in_b[0] + 2 * EDIM, out_b[0],
                       wh + 0 * WSTRIDE + WOFF_VO, bvo + 0 * EDIM};
        FuseArgs f1 = {out_w[1], in_w[1] + 2 * EDIM * EDIM, in_b[1] + 2 * EDIM, out_b[1],
                       wh + 1 * WSTRIDE + WOFF_VO, bvo + 1 * EDIM};
        fuse_w_kernel<<<dim3(17, 16, 2), dim3(16, 16)>>>(f0, f1);
    }

    // ---- main pipeline (both streams via blockIdx.z) ----
    // stream 0 (dna side) attends over mol (xh+MN); stream 1 over dna (xh+0)
    // gemm A -> Y
    {
        GArgs a0 = {xh + MN, wh + 0 * WSTRIDE + WOFF_VO, bvo + 0 * EDIM, Y + 0 * MN, nullptr};
        GArgs a1 = {xh,      wh + 1 * WSTRIDE + WOFF_VO, bvo + 1 * EDIM, Y + 1 * MN, nullptr};
        gemm_mma<0><<<dim3(EDIM / BN, MROWS / BM, 2), NTHR, DYN_SMEM>>>(
            a0, a1, EDIM, EDIM, EDIM, EDIM, 0);
    }
    // ln1 -> x1 (fp32 + fp16)
    {
        LArgs l0 = {dna, Y + 0 * MN, lnA_g[0], lnA_b[0], x1f,      x1h,      nullptr, 0};
        LArgs l1 = {mol, Y + 1 * MN, lnA_g[1], lnA_b[1], x1f + MN, x1h + MN, nullptr, 0};
        ln_kernel<0><<<dim3(MROWS / 8, 1, 2), 256>>>(l0, l1, 0);
    }
    // gemm B (FFN up + relu) -> H (fp16)
    {
        GArgs a0 = {x1h,      wh + 0 * WSTRIDE + WOFF_W1, b1[0], nullptr, hh};
        GArgs a1 = {x1h + MN, wh + 1 * WSTRIDE + WOFF_W1, b1[1], nullptr, hh + MH};
        gemm_mma<1><<<dim3(HDIM / BN, MROWS / BM, 2), NTHR, DYN_SMEM>>>(
            a0, a1, EDIM, EDIM, EDIM, 0, HDIM);
    }
    // gemm C (FFN down) -> Y
    {
        GArgs a0 = {hh,      wh + 0 * WSTRIDE + WOFF_W2, b2[0], Y + 0 * MN, nullptr};
        GArgs a1 = {hh + MH, wh + 1 * WSTRIDE + WOFF_W2, b2[1], Y + 1 * MN, nullptr};
        gemm_mma<0><<<dim3(EDIM / BN, MROWS / BM, 2), NTHR, DYN_SMEM>>>(
            a0, a1, HDIM, HDIM, HDIM, EDIM, 0);
    }
    // ln2 -> output halves
    {
        LArgs l0 = {x1f,      Y + 0 * MN, lnC_g[0], lnC_b[0], nullptr, nullptr, out, 0};
        LArgs l1 = {x1f + MN, Y + 1 * MN, lnC_g[1], lnC_b[1], nullptr, nullptr, out, EDIM};
        ln_kernel<1><<<dim3(MROWS / 8, 1, 2), 256>>>(l0, l1, 2 * EDIM);
    }
}